// round 14
// baseline (speedup 1.0000x reference)
#include <cuda_runtime.h>
#include <cuda_bf16.h>
#include <math.h>
#include <stdint.h>

// Problem constants
#define MROWS 8192      // B*S
#define DDIM  512
#define HNUM  8
#define KHD   64
#define FFD   2048
#define ENUM  4
#define SLEN  1024
#define BNUM  8
#define QKVW  1536
#define CROWS (MROWS + 128)   // compact rows + mean-row margin

// ===================== scratch (device globals) ==============================
__device__ __nv_bfloat16 g_xbf  [MROWS * 2 * DDIM];     // embedding, split
__device__ __nv_bfloat16 g_qkvbf[MROWS * 2 * QKVW];     // shared qkv, split
__device__ __nv_bfloat16 g_attbf[MROWS * 2 * DDIM];     // shared attn out split
__device__ int   g_idx[MROWS];
__device__ int   g_cnt[ENUM * BNUM];
__device__ int   g_segoff[ENUM * BNUM];
__device__ int   g_ne[ENUM];
__device__ int   g_pos[MROWS];
__device__ int   g_s2t[ENUM * MROWS];                    // compact slot -> token
__device__ float g_meanS[ENUM * BNUM];
__device__ float g_totalS[BNUM];
__device__ float g_c2[FFD * ENUM];                       // W2@Wg
__device__ float g_c1[DDIM * ENUM];                      // W1@c2
__device__ float g_c0[DDIM * ENUM];                      // Wo@c1 (gate matrix)
__device__ float g_v2[ENUM * FFD];                       // eW2@Wout
__device__ float g_v1[ENUM * DDIM];                      // eW1@v2
__device__ float g_v0[ENUM * DDIM];                      // eWo@v1 (expert out vector)
__device__ __align__(16) unsigned char g_zerobuf[16];

// per-expert compact buffers
__device__ __nv_bfloat16 g_qkvcbf[ENUM * MROWS * 2 * QKVW];  // compact qkv split
__device__ float         g_catt  [ENUM * CROWS * DDIM];      // compact attn + mean rows

// weights: bf16 hi|lo split. *_T = transposed [N, 2K]; *_A = row-split [M, 2K]
__device__ __nv_bfloat16 g_swqkv  [QKVW * 2 * DDIM];
__device__ __nv_bfloat16 g_sw1    [FFD  * 2 * DDIM];
__device__ __nv_bfloat16 g_sw2    [DDIM * 2 * FFD];
__device__ __nv_bfloat16 g_swoA   [DDIM * 2 * DDIM];
__device__ __nv_bfloat16 g_scmb1  [DDIM * 2 * FFD];      // Wo@W1 (A-format)
__device__ __nv_bfloat16 g_cmbA   [DDIM * 2 * DDIM];     // Wo@W1@W2 row-major split
__device__ __nv_bfloat16 g_ewqkv  [ENUM * QKVW * 2 * DDIM];
__device__ __nv_bfloat16 g_ecmbQKV[ENUM * QKVW * 2 * DDIM];  // (cmb@eWqkv)^T split

// ===================== PTX helpers (base ISA only) ==========================
__device__ __forceinline__ uint32_t smem_u32(const void* p) {
    uint32_t a;
    asm("{ .reg .u64 t; cvta.to.shared.u64 t, %1; cvt.u32.u64 %0, t; }"
        : "=r"(a) : "l"(p));
    return a;
}
__device__ __forceinline__ void cp16(uint32_t dst, const void* src) {
    asm volatile("cp.async.cg.shared.global [%0], [%1], 16;"
                 :: "r"(dst), "l"(src) : "memory");
}
__device__ __forceinline__ void ldsm_x4(uint32_t& r0, uint32_t& r1,
                                        uint32_t& r2, uint32_t& r3, uint32_t addr) {
    asm volatile("ldmatrix.sync.aligned.m8n8.x4.shared.b16 {%0,%1,%2,%3}, [%4];"
                 : "=r"(r0), "=r"(r1), "=r"(r2), "=r"(r3) : "r"(addr));
}
__device__ __forceinline__ void ldsm_x4_t(uint32_t& r0, uint32_t& r1,
                                          uint32_t& r2, uint32_t& r3, uint32_t addr) {
    asm volatile("ldmatrix.sync.aligned.m8n8.x4.trans.shared.b16 {%0,%1,%2,%3}, [%4];"
                 : "=r"(r0), "=r"(r1), "=r"(r2), "=r"(r3) : "r"(addr));
}
__device__ __forceinline__ void mma16816(float* c, const uint32_t* a, const uint32_t* b) {
    asm volatile("mma.sync.aligned.m16n8k16.row.col.f32.bf16.bf16.f32 "
                 "{%0,%1,%2,%3}, {%4,%5,%6,%7}, {%8,%9}, {%0,%1,%2,%3};"
                 : "+f"(c[0]), "+f"(c[1]), "+f"(c[2]), "+f"(c[3])
                 : "r"(a[0]), "r"(a[1]), "r"(a[2]), "r"(a[3]),
                   "r"(b[0]), "r"(b[1]));
}
__device__ __forceinline__ void split_bf16(float x, __nv_bfloat16& hi, __nv_bfloat16& lo) {
    hi = __float2bfloat16(x);
    lo = __float2bfloat16(x - __bfloat162float(hi));
}
__device__ __forceinline__ uint32_t pack_bf2(__nv_bfloat16 a, __nv_bfloat16 b) {
    __nv_bfloat162 t = __halves2bfloat162(a, b);
    return *(uint32_t*)&t;
}

// ===================== embedding gather (split output) ======================
__global__ void k_gather(const int* __restrict__ tok,
                         const float* __restrict__ emb,
                         __nv_bfloat16* __restrict__ xbf)
{
    int t  = blockIdx.x * blockDim.x + threadIdx.x;
    int i  = t >> 7;
    int c4 = t & 127;
    float4 v = ((const float4*)(emb + (size_t)tok[i] * DDIM))[c4];
    float xv[4] = {v.x, v.y, v.z, v.w};
    __nv_bfloat16 hi[4], lo[4];
#pragma unroll
    for (int j = 0; j < 4; j++) split_bf16(xv[j], hi[j], lo[j]);
    __nv_bfloat16* row = xbf + (size_t)i * (2 * DDIM);
    *(uint64_t*)(row + c4 * 4)        = *(uint64_t*)hi;
    *(uint64_t*)(row + DDIM + c4 * 4) = *(uint64_t*)lo;
}

// ===================== weight conversion kernels ============================
__global__ void k_cvt_wt(const float* __restrict__ W, size_t wSz,
                         __nv_bfloat16* __restrict__ Y, size_t ySz,
                         int K, int N)
{
    W += (size_t)blockIdx.z * wSz;
    Y += (size_t)blockIdx.z * ySz;
    __shared__ float tile[32][33];
    int k0 = blockIdx.y * 32, n0 = blockIdx.x * 32;
    int tx = threadIdx.x, ty = threadIdx.y;   // 32 x 8
#pragma unroll
    for (int i = 0; i < 32; i += 8)
        tile[ty + i][tx] = W[(size_t)(k0 + ty + i) * N + n0 + tx];
    __syncthreads();
#pragma unroll
    for (int i = 0; i < 32; i += 8) {
        float x = tile[tx][ty + i];
        __nv_bfloat16 hi, lo; split_bf16(x, hi, lo);
        size_t base = (size_t)(n0 + ty + i) * (2 * K) + k0 + tx;
        Y[base]     = hi;
        Y[base + K] = lo;
    }
}

__global__ void k_cvt_qkv(const float* __restrict__ Wq_, const float* __restrict__ Wk_,
                          const float* __restrict__ Wv_, size_t wSz,
                          __nv_bfloat16* __restrict__ Y, size_t ySz)
{
    int e = blockIdx.z / 3, which = blockIdx.z % 3;
    const float* W = (which == 0) ? Wq_ : (which == 1) ? Wk_ : Wv_;
    W += (size_t)e * wSz;
    __nv_bfloat16* Yp = Y + (size_t)e * ySz + (size_t)which * (DDIM * 2 * DDIM);
    __shared__ float tile[32][33];
    int k0 = blockIdx.y * 32, n0 = blockIdx.x * 32;
    int tx = threadIdx.x, ty = threadIdx.y;
#pragma unroll
    for (int i = 0; i < 32; i += 8)
        tile[ty + i][tx] = W[(size_t)(k0 + ty + i) * DDIM + n0 + tx];
    __syncthreads();
#pragma unroll
    for (int i = 0; i < 32; i += 8) {
        float x = tile[tx][ty + i];
        __nv_bfloat16 hi, lo; split_bf16(x, hi, lo);
        size_t base = (size_t)(n0 + ty + i) * (2 * DDIM) + k0 + tx;
        Yp[base]        = hi;
        Yp[base + DDIM] = lo;
    }
}

__global__ void k_cvt_a(const float* __restrict__ W, size_t wSz,
                        __nv_bfloat16* __restrict__ Y, size_t ySz)
{
    W += (size_t)blockIdx.z * wSz;
    Y += (size_t)blockIdx.z * ySz;
    int t  = blockIdx.x * blockDim.x + threadIdx.x;
    int r  = t >> 7;
    int c4 = t & 127;
    float4 v = ((const float4*)(W + (size_t)r * DDIM))[c4];
    float xv[4] = {v.x, v.y, v.z, v.w};
    __nv_bfloat16 hi[4], lo[4];
#pragma unroll
    for (int j = 0; j < 4; j++) split_bf16(xv[j], hi[j], lo[j]);
    __nv_bfloat16* row = Y + (size_t)r * (2 * DDIM);
    *(uint64_t*)(row + c4 * 4)        = *(uint64_t*)hi;
    *(uint64_t*)(row + DDIM + c4 * 4) = *(uint64_t*)lo;
}

// ===================== fp32 matvec: o[r] = W[r,:] . v (z-batched) ===========
__global__ void k_matv(const float* __restrict__ W, size_t wSz,
                       const float* __restrict__ v, size_t vSz,
                       float* __restrict__ o, size_t oSz, int K)
{
    W += (size_t)blockIdx.z * wSz;
    v += (size_t)blockIdx.z * vSz;
    o += (size_t)blockIdx.z * oSz;
    int r = blockIdx.x * 8 + (threadIdx.x >> 5);
    int lane = threadIdx.x & 31;
    const float* wr = W + (size_t)r * K;
    float s = 0.0f;
    for (int k = lane; k < K; k += 32) s = fmaf(wr[k], v[k], s);
#pragma unroll
    for (int off = 16; off; off >>= 1) s += __shfl_down_sync(0xffffffffu, s, off);
    if (lane == 0) o[r] = s;
}

// ===================== mma.sync bf16x3 GEMM — fused 3-product ===============
// Pass order hh -> hl -> lh keeps a_hi live and both b halves in registers:
// 12 ldsm_x4 per k16 step instead of 16 (-25% smem reads).
#define G3_STAGE 32768
#define G3_SMEM  (3 * G3_STAGE)

__global__ __launch_bounds__(256, 2)
void k_gemm3(const __nv_bfloat16* __restrict__ Ag, size_t aSz,
             const __nv_bfloat16* __restrict__ Bg, size_t bSz,
             float* __restrict__ Cf, size_t cSz,
             __nv_bfloat16* __restrict__ Y, size_t ySz,
             int N, int K,
             const int* __restrict__ nptr, int nconst, int nadd,
             const int* __restrict__ s2t)
{
    const int z = blockIdx.z;
    Ag += (size_t)z * aSz;
    Bg += (size_t)z * bSz;
    const int n = (nptr ? __ldg(nptr + z) : nconst) + nadd;
    const int mbase = blockIdx.y * 128;
    if (mbase >= n) return;
    if (Cf) Cf += (size_t)z * cSz;
    if (Y)  Y  += (size_t)z * ySz;
    const int* s2tz = s2t ? (s2t + (size_t)z * MROWS) : nullptr;

    extern __shared__ __align__(128) unsigned char smem[];
    const uint32_t sbase = smem_u32(smem);
    const int tid  = threadIdx.x;
    const int wid  = tid >> 5;
    const int lane = tid & 31;

    const int nbase = blockIdx.x * 128;
    const int K2    = 2 * K;
    const int NCP   = K / 32;

    const int mo = (wid >> 2) * 64;
    const int no = (wid & 3) * 32;

    auto fill = [&](int c) {
        int s   = c % 3;
        int col = c * 32;
        uint32_t base = sbase + s * G3_STAGE;
#pragma unroll
        for (int i2 = 0; i2 < 2; i2++) {
            int ch = tid + i2 * 256;
            int r  = ch >> 2, cc = ch & 3;
            uint32_t off = (uint32_t)(r * 64) + (uint32_t)((cc ^ ((r >> 1) & 3)) << 4);
            int grow = mbase + r;
            bool act = grow < n;
            int arowi = (s2tz && act) ? __ldg(s2tz + grow) : grow;
            const __nv_bfloat16* arow = Ag + (size_t)arowi * K2 + col + cc * 8;
            cp16(base + off, act ? (const void*)arow : (const void*)g_zerobuf);
            cp16(base + 8192 + off, act ? (const void*)(arow + K) : (const void*)g_zerobuf);
            const __nv_bfloat16* brow = Bg + (size_t)(nbase + r) * K2 + col + cc * 8;
            cp16(base + 16384 + off, brow);
            cp16(base + 24576 + off, brow + K);
        }
        asm volatile("cp.async.commit_group;" ::: "memory");
    };

    float acc[4][4][4];
#pragma unroll
    for (int i = 0; i < 4; i++)
#pragma unroll
        for (int j = 0; j < 4; j++)
#pragma unroll
            for (int t = 0; t < 4; t++) acc[i][j][t] = 0.0f;

    fill(0);
    if (NCP > 1) fill(1);

    for (int c = 0; c < NCP; c++) {
        if (c + 1 < NCP) asm volatile("cp.async.wait_group 1;" ::: "memory");
        else             asm volatile("cp.async.wait_group 0;" ::: "memory");
        __syncthreads();

        if (c + 2 < NCP) fill(c + 2);

        uint32_t sA = sbase + (c % 3) * G3_STAGE;
        uint32_t sB = sA + 16384;

#pragma unroll
        for (int kk = 0; kk < 2; kk++) {
            uint32_t a[4][4];
            uint32_t bh[4][2], bl[4][2];
            int achk = 2 * kk + (lane >> 4);
            int arow0 = lane & 15;
            int bchk = 2 * kk + ((lane >> 3) & 1);
            int brow0 = (lane & 7) + ((lane >> 4) << 3);

            // load a_hi + b_hi + b_lo (b halves stay live all 3 passes)
#pragma unroll
            for (int i = 0; i < 4; i++) {
                int row = mo + i * 16 + arow0;
                ldsm_x4(a[i][0], a[i][1], a[i][2], a[i][3],
                        sA + row * 64 + (uint32_t)(((achk ^ ((row >> 1) & 3))) << 4));
            }
#pragma unroll
            for (int jj = 0; jj < 2; jj++) {
                int nrow = no + jj * 16 + brow0;
                uint32_t boff = (uint32_t)(nrow * 64)
                              + (uint32_t)(((bchk ^ ((nrow >> 1) & 3))) << 4);
                ldsm_x4(bh[2 * jj][0], bh[2 * jj][1], bh[2 * jj + 1][0], bh[2 * jj + 1][1],
                        sB + boff);
                ldsm_x4(bl[2 * jj][0], bl[2 * jj][1], bl[2 * jj + 1][0], bl[2 * jj + 1][1],
                        sB + 8192 + boff);
            }

            // pass hh: a_hi x b_hi
#pragma unroll
            for (int i = 0; i < 4; i++)
#pragma unroll
                for (int j = 0; j < 4; j++)
                    mma16816(acc[i][j], a[i], bh[j]);

            // pass hl: a_hi x b_lo (a_hi still live)
#pragma unroll
            for (int i = 0; i < 4; i++)
#pragma unroll
                for (int j = 0; j < 4; j++)
                    mma16816(acc[i][j], a[i], bl[j]);

            // pass lh: a_lo x b_hi
#pragma unroll
            for (int i = 0; i < 4; i++) {
                int row = mo + i * 16 + arow0;
                ldsm_x4(a[i][0], a[i][1], a[i][2], a[i][3],
                        sA + 8192 + row * 64 + (uint32_t)(((achk ^ ((row >> 1) & 3))) << 4));
            }
#pragma unroll
            for (int i = 0; i < 4; i++)
#pragma unroll
                for (int j = 0; j < 4; j++)
                    mma16816(acc[i][j], a[i], bh[j]);
        }
    }

    int rbase = mbase + mo + (lane >> 2);
    int cbase = nbase + no + (lane & 3) * 2;
#pragma unroll
    for (int i = 0; i < 4; i++) {
        int r0 = rbase + i * 16, r1 = r0 + 8;
#pragma unroll
        for (int j = 0; j < 4; j++) {
            int col = cbase + j * 8;
            if (Cf) {
                if (r0 < n)
                    *(float2*)(Cf + (size_t)r0 * N + col) = make_float2(acc[i][j][0], acc[i][j][1]);
                if (r1 < n)
                    *(float2*)(Cf + (size_t)r1 * N + col) = make_float2(acc[i][j][2], acc[i][j][3]);
            }
            if (Y) {
                if (r0 < n) {
                    __nv_bfloat16 h0, l0, h1, l1;
                    split_bf16(acc[i][j][0], h0, l0);
                    split_bf16(acc[i][j][1], h1, l1);
                    *(__nv_bfloat162*)(Y + (size_t)r0 * 2 * N + col)     = __halves2bfloat162(h0, h1);
                    *(__nv_bfloat162*)(Y + (size_t)r0 * 2 * N + N + col) = __halves2bfloat162(l0, l1);
                }
                if (r1 < n) {
                    __nv_bfloat16 h0, l0, h1, l1;
                    split_bf16(acc[i][j][2], h0, l0);
                    split_bf16(acc[i][j][3], h1, l1);
                    *(__nv_bfloat162*)(Y + (size_t)r1 * 2 * N + col)     = __halves2bfloat162(h0, h1);
                    *(__nv_bfloat162*)(Y + (size_t)r1 * 2 * N + N + col) = __halves2bfloat162(l0, l1);
                }
            }
        }
    }
}

// ===================== MMA flash attention (shared block) ===================
#define ATT_SMEM 98304   // Q 32KB + 2 x (K/V hi/lo 32KB)

__global__ __launch_bounds__(256)
void k_attn_mma(const __nv_bfloat16* __restrict__ QKVs,
                __nv_bfloat16* __restrict__ Oy)
{
    extern __shared__ __align__(128) unsigned char smem[];
    const uint32_t sb = smem_u32(smem);
    const int tid = threadIdx.x, wid = tid >> 5, lane = tid & 31;
    const int bh = blockIdx.y, b = bh >> 3, h = bh & 7;
    const int q0 = blockIdx.x * 128;

    const uint32_t QH = sb, QL = sb + 16384;

#pragma unroll
    for (int i = 0; i < 8; i++) {
        int id = tid + i * 256;
        int half = id >> 10, rem = id & 1023;
        int qr = rem >> 3, c = rem & 7;
        const __nv_bfloat16* src = QKVs
            + (size_t)(b * SLEN + q0 + qr) * (2 * QKVW)
            + (size_t)half * QKVW + h * KHD + c * 8;
        cp16((half ? QL : QH) + qr * 128 + (uint32_t)((c ^ (qr & 7)) << 4), src);
    }
    asm volatile("cp.async.commit_group;" ::: "memory");

    auto fillkv = [&](int kc) {
        uint32_t base = sb + 32768 + (uint32_t)(kc & 1) * 32768;
#pragma unroll
        for (int i = 0; i < 8; i++) {
            int id = tid + i * 256;
            int sub = id >> 9, rem = id & 511;
            int kr = rem >> 3, c = rem & 7;
            int col = (sub == 0) ? (DDIM + h * KHD)
                    : (sub == 1) ? (QKVW + DDIM + h * KHD)
                    : (sub == 2) ? (2 * DDIM + h * KHD)
                                 : (QKVW + 2 * DDIM + h * KHD);
            const __nv_bfloat16* src = QKVs
                + (size_t)(b * SLEN + kc * 64 + kr) * (2 * QKVW) + col + c * 8;
            cp16(base + sub * 8192 + kr * 128 + (uint32_t)((c ^ (kr & 7)) << 4), src);
        }
        asm volatile("cp.async.commit_group;" ::: "memory");
    };

    fillkv(0);
    asm volatile("cp.async.wait_group 0;" ::: "memory");
    __syncthreads();

    uint32_t qh[4][4], ql[4][4];
    {
        int arow = wid * 16 + (lane & 15);
        int cb = lane >> 4;
#pragma unroll
        for (int kk = 0; kk < 4; kk++) {
            int chk = 2 * kk + cb;
            uint32_t off = (uint32_t)(arow * 128) + (uint32_t)((chk ^ (arow & 7)) << 4);
            ldsm_x4(qh[kk][0], qh[kk][1], qh[kk][2], qh[kk][3], QH + off);
            ldsm_x4(ql[kk][0], ql[kk][1], ql[kk][2], ql[kk][3], QL + off);
        }
    }

    float o[8][4];
#pragma unroll
    for (int t = 0; t < 8; t++)
#pragma unroll
        for (int i = 0; i < 4; i++) o[t][i] = 0.0f;
    float m0 = -INFINITY, m1 = -INFINITY, l0 = 0.0f, l1 = 0.0f;

    const int krow0 = (lane & 7) + ((lane >> 4) << 3);
    const int kchkb = (lane >> 3) & 1;
    const int vrow0 = lane & 15;
    const int vchkb = lane >> 4;

    for (int kc = 0; kc < 16; kc++) {
        if (kc) {
            asm volatile("cp.async.wait_group 0;" ::: "memory");
            __syncthreads();
        }
        if (kc + 1 < 16) fillkv(kc + 1);

        uint32_t KB  = sb + 32768 + (uint32_t)(kc & 1) * 32768;
        uint32_t KHs = KB, KLs = KB + 8192, VHs = KB + 16384, VLs = KB + 24576;

        float s[8][4];
#pragma unroll
        for (int t = 0; t < 8; t++)
#pragma unroll
            for (int i = 0; i < 4; i++) s[t][i] = 0.0f;

#pragma unroll
        for (int kk = 0; kk < 4; kk++) {
#pragma unroll
            for (int jj = 0; jj < 4; jj++) {
                int nr = jj * 16 + krow0;
                int chk = 2 * kk + kchkb;
                uint32_t addr = (uint32_t)(nr * 128) + (uint32_t)((chk ^ (nr & 7)) << 4);
                uint32_t bb[4];
                ldsm_x4(bb[0], bb[1], bb[2], bb[3], KHs + addr);
                mma16816(s[2 * jj],     qh[kk], bb + 0);
                mma16816(s[2 * jj + 1], qh[kk], bb + 2);
                mma16816(s[2 * jj],     ql[kk], bb + 0);
                mma16816(s[2 * jj + 1], ql[kk], bb + 2);
                ldsm_x4(bb[0], bb[1], bb[2], bb[3], KLs + addr);
                mma16816(s[2 * jj],     qh[kk], bb + 0);
                mma16816(s[2 * jj + 1], qh[kk], bb + 2);
            }
        }

#pragma unroll
        for (int t = 0; t < 8; t++)
#pragma unroll
            for (int i = 0; i < 4; i++) s[t][i] *= 0.125f;

        float rm0 = -INFINITY, rm1 = -INFINITY;
#pragma unroll
        for (int t = 0; t < 8; t++) {
            rm0 = fmaxf(rm0, fmaxf(s[t][0], s[t][1]));
            rm1 = fmaxf(rm1, fmaxf(s[t][2], s[t][3]));
        }
        rm0 = fmaxf(rm0, __shfl_xor_sync(0xffffffffu, rm0, 1));
        rm0 = fmaxf(rm0, __shfl_xor_sync(0xffffffffu, rm0, 2));
        rm1 = fmaxf(rm1, __shfl_xor_sync(0xffffffffu, rm1, 1));
        rm1 = fmaxf(rm1, __shfl_xor_sync(0xffffffffu, rm1, 2));

        float mn0 = fmaxf(m0, rm0), mn1 = fmaxf(m1, rm1);
        float cr0 = __expf(m0 - mn0), cr1 = __expf(m1 - mn1);
        float sum0 = 0.0f, sum1 = 0.0f;
#pragma unroll
        for (int t = 0; t < 8; t++) {
            s[t][0] = __expf(s[t][0] - mn0);
            s[t][1] = __expf(s[t][1] - mn0);
            s[t][2] = __expf(s[t][2] - mn1);
            s[t][3] = __expf(s[t][3] - mn1);
            sum0 += s[t][0] + s[t][1];
            sum1 += s[t][2] + s[t][3];
        }
        sum0 += __shfl_xor_sync(0xffffffffu, sum0, 1);
        sum0 += __shfl_xor_sync(0xffffffffu, sum0, 2);
        sum1 += __shfl_xor_sync(0xffffffffu, sum1, 1);
        sum1 += __shfl_xor_sync(0xffffffffu, sum1, 2);
        l0 = l0 * cr0 + sum0;
        l1 = l1 * cr1 + sum1;
#pragma unroll
        for (int t = 0; t < 8; t++) {
            o[t][0] *= cr0; o[t][1] *= cr0;
            o[t][2] *= cr1; o[t][3] *= cr1;
        }
        m0 = mn0; m1 = mn1;

#pragma unroll
        for (int kk = 0; kk < 4; kk++) {
            uint32_t ph[4], pl[4];
            {
                __nv_bfloat16 hi0, lo0, hi1, lo1;
                split_bf16(s[2 * kk][0], hi0, lo0);
                split_bf16(s[2 * kk][1], hi1, lo1);
                ph[0] = pack_bf2(hi0, hi1);  pl[0] = pack_bf2(lo0, lo1);
                split_bf16(s[2 * kk][2], hi0, lo0);
                split_bf16(s[2 * kk][3], hi1, lo1);
                ph[1] = pack_bf2(hi0, hi1);  pl[1] = pack_bf2(lo0, lo1);
                split_bf16(s[2 * kk + 1][0], hi0, lo0);
                split_bf16(s[2 * kk + 1][1], hi1, lo1);
                ph[2] = pack_bf2(hi0, hi1);  pl[2] = pack_bf2(lo0, lo1);
                split_bf16(s[2 * kk + 1][2], hi0, lo0);
                split_bf16(s[2 * kk + 1][3], hi1, lo1);
                ph[3] = pack_bf2(hi0, hi1);  pl[3] = pack_bf2(lo0, lo1);
            }
            int kr = kk * 16 + vrow0;
#pragma unroll
            for (int cp = 0; cp < 4; cp++) {
                int chk = 2 * cp + vchkb;
                uint32_t addr = (uint32_t)(kr * 128) + (uint32_t)((chk ^ (kr & 7)) << 4);
                uint32_t bv[4];
                ldsm_x4_t(bv[0], bv[1], bv[2], bv[3], VHs + addr);
                mma16816(o[2 * cp],     ph, bv + 0);
                mma16816(o[2 * cp + 1], ph, bv + 2);
                mma16816(o[2 * cp],     pl, bv + 0);
                mma16816(o[2 * cp + 1], pl, bv + 2);
                ldsm_x4_t(bv[0], bv[1], bv[2], bv[3], VLs + addr);
                mma16816(o[2 * cp],     ph, bv + 0);
                mma16816(o[2 * cp + 1], ph, bv + 2);
            }
        }
        __syncthreads();
    }

    float i0 = 1.0f / l0, i1 = 1.0f / l1;
    size_t g0 = (size_t)(b * SLEN + q0 + wid * 16 + (lane >> 2));
    size_t g1 = g0 + 8;
    int col0 = h * KHD + 2 * (lane & 3);
#pragma unroll
    for (int t = 0; t < 8; t++) {
        int col = col0 + t * 8;
        float v0 = o[t][0] * i0, v1 = o[t][1] * i0;
        float v2 = o[t][2] * i1, v3 = o[t][3] * i1;
        __nv_bfloat16 h0, ll0, h1, ll1;
        split_bf16(v0, h0, ll0); split_bf16(v1, h1, ll1);
        *(__nv_bfloat162*)(Oy + g0 * (2 * DDIM) + col)        = __halves2bfloat162(h0, h1);
        *(__nv_bfloat162*)(Oy + g0 * (2 * DDIM) + DDIM + col) = __halves2bfloat162(ll0, ll1);
        split_bf16(v2, h0, ll0); split_bf16(v3, h1, ll1);
        *(__nv_bfloat162*)(Oy + g1 * (2 * DDIM) + col)        = __halves2bfloat162(h0, h1);
        *(__nv_bfloat162*)(Oy + g1 * (2 * DDIM) + DDIM + col) = __halves2bfloat162(ll0, ll1);
    }
}

// ===================== MMA flash attention (compact experts, fp32 out) ======
__global__ __launch_bounds__(256)
void k_attn_mma_c(const __nv_bfloat16* __restrict__ qkvcbf,
                  float* __restrict__ cattf,
                  const int* __restrict__ cnt32, const int* __restrict__ seg32)
{
    const int e  = blockIdx.z;
    const int bh = blockIdx.y;
    const int b  = bh >> 3, h = bh & 7;
    const int cnt = __ldg(cnt32 + e * BNUM + b);
    const int q0  = blockIdx.x * 128;
    if (q0 >= cnt) return;
    const int seg = __ldg(seg32 + e * BNUM + b);

    const __nv_bfloat16* QKVs = qkvcbf + (size_t)e * MROWS * (2 * QKVW);
    float* Of = cattf + (size_t)e * CROWS * DDIM;

    extern __shared__ __align__(128) unsigned char smem[];
    const uint32_t sb = smem_u32(smem);
    const int tid = threadIdx.x, wid = tid >> 5, lane = tid & 31;

    const uint32_t QH = sb, QL = sb + 16384;

#pragma unroll
    for (int i = 0; i < 8; i++) {
        int id = tid + i * 256;
        int half = id >> 10, rem = id & 1023;
        int qr = rem >> 3, c = rem & 7;
        int qrow = q0 + qr; if (qrow >= cnt) qrow = cnt - 1;
        const __nv_bfloat16* src = QKVs
            + (size_t)(seg + qrow) * (2 * QKVW)
            + (size_t)half * QKVW + h * KHD + c * 8;
        cp16((half ? QL : QH) + qr * 128 + (uint32_t)((c ^ (qr & 7)) << 4), src);
    }
    asm volatile("cp.async.commit_group;" ::: "memory");

    const int NKC = (cnt + 63) >> 6;

    auto fillkv = [&](int kc) {
        uint32_t base = sb + 32768 + (uint32_t)(kc & 1) * 32768;
#pragma unroll
        for (int i = 0; i < 8; i++) {
            int id = tid + i * 256;
            int sub = id >> 9, rem = id & 511;
            int kr = rem >> 3, c = rem & 7;
            int col = (sub == 0) ? (DDIM + h * KHD)
                    : (sub == 1) ? (QKVW + DDIM + h * KHD)
                    : (sub == 2) ? (2 * DDIM + h * KHD)
                                 : (QKVW + 2 * DDIM + h * KHD);
            bool act = (kc * 64 + kr) < cnt;
            const void* src = act
                ? (const void*)(QKVs + (size_t)(seg + kc * 64 + kr) * (2 * QKVW) + col + c * 8)
                : (const void*)g_zerobuf;
            cp16(base + sub * 8192 + kr * 128 + (uint32_t)((c ^ (kr & 7)) << 4), src);
        }
        asm volatile("cp.async.commit_group;" ::: "memory");
    };

    fillkv(0);
    asm volatile("cp.async.wait_group 0;" ::: "memory");
    __syncthreads();

    uint32_t qh[4][4], ql[4][4];
    {
        int arow = wid * 16 + (lane & 15);
        int cb = lane >> 4;
#pragma unroll
        for (int kk = 0; kk < 4; kk++) {
            int chk = 2 * kk + cb;
            uint32_t off = (uint32_t)(arow * 128) + (uint32_t)((chk ^ (arow & 7)) << 4);
            ldsm_x4(qh[kk][0], qh[kk][1], qh[kk][2], qh[kk][3], QH + off);
            ldsm_x4(ql[kk][0], ql[kk][1], ql[kk][2], ql[kk][3], QL + off);
        }
    }

    float o[8][4];
#pragma unroll
    for (int t = 0; t < 8; t++)
#pragma unroll
        for (int i = 0; i < 4; i++) o[t][i] = 0.0f;
    float m0 = 0.0f, m1 = 0.0f;
    float l0 = (float)(SLEN - cnt), l1 = (float)(SLEN - cnt);

    const int krow0 = (lane & 7) + ((lane >> 4) << 3);
    const int kchkb = (lane >> 3) & 1;
    const int vrow0 = lane & 15;
    const int vchkb = lane >> 4;
    const int ncol0 = 2 * (lane & 3);

    for (int kc = 0; kc < NKC; kc++) {
        if (kc) {
            asm volatile("cp.async.wait_group 0;" ::: "memory");
            __syncthreads();
        }
        if (kc + 1 < NKC) fillkv(kc + 1);

        uint32_t KB  = sb + 32768 + (uint32_t)(kc & 1) * 32768;
        uint32_t KHs = KB, KLs = KB + 8192, VHs = KB + 16384, VLs = KB + 24576;

        float s[8][4];
#pragma unroll
        for (int t = 0; t < 8; t++)
#pragma unroll
            for (int i = 0; i < 4; i++) s[t][i] = 0.0f;

#pragma unroll
        for (int kk = 0; kk < 4; kk++) {
#pragma unroll
            for (int jj = 0; jj < 4; jj++) {
                int nr = jj * 16 + krow0;
                int chk = 2 * kk + kchkb;
                uint32_t addr = (uint32_t)(nr * 128) + (uint32_t)((chk ^ (nr & 7)) << 4);
                uint32_t bb[4];
                ldsm_x4(bb[0], bb[1], bb[2], bb[3], KHs + addr);
                mma16816(s[2 * jj],     qh[kk], bb + 0);
                mma16816(s[2 * jj + 1], qh[kk], bb + 2);
                mma16816(s[2 * jj],     ql[kk], bb + 0);
                mma16816(s[2 * jj + 1], ql[kk], bb + 2);
                ldsm_x4(bb[0], bb[1], bb[2], bb[3], KLs + addr);
                mma16816(s[2 * jj],     qh[kk], bb + 0);
                mma16816(s[2 * jj + 1], qh[kk], bb + 2);
            }
        }

        int rem = cnt - kc * 64;
#pragma unroll
        for (int t = 0; t < 8; t++) {
            int c0 = t * 8 + ncol0;
#pragma unroll
            for (int i = 0; i < 4; i++) {
                int colk = c0 + (i & 1);
                s[t][i] = (colk < rem) ? s[t][i] * 0.125f : -1e30f;
            }
        }

        float rm0 = -INFINITY, rm1 = -INFINITY;
#pragma unroll
        for (int t = 0; t < 8; t++) {
            rm0 = fmaxf(rm0, fmaxf(s[t][0], s[t][1]));
            rm1 = fmaxf(rm1, fmaxf(s[t][2], s[t][3]));
        }
        rm0 = fmaxf(rm0, __shfl_xor_sync(0xffffffffu, rm0, 1));
        rm0 = fmaxf(rm0, __shfl_xor_sync(0xffffffffu, rm0, 2));
        rm1 = fmaxf(rm1, __shfl_xor_sync(0xffffffffu, rm1, 1));
        rm1 = fmaxf(rm1, __shfl_xor_sync(0xffffffffu, rm1, 2));

        float mn0 = fmaxf(m0, rm0), mn1 = fmaxf(m1, rm1);
        float cr0 = __expf(m0 - mn0), cr1 = __expf(m1 - mn1);
        float sum0 = 0.0f, sum1 = 0.0f;
#pragma unroll
        for (int t = 0; t < 8; t++) {
            s[t][0] = __expf(s[t][0] - mn0);
            s[t][1] = __expf(s[t][1] - mn0);
            s[t][2] = __expf(s[t][2] - mn1);
            s[t][3] = __expf(s[t][3] - mn1);
            sum0 += s[t][0] + s[t][1];
            sum1 += s[t][2] + s[t][3];
        }
        sum0 += __shfl_xor_sync(0xffffffffu, sum0, 1);
        sum0 += __shfl_xor_sync(0xffffffffu, sum0, 2);
        sum1 += __shfl_xor_sync(0xffffffffu, sum1, 1);
        sum1 += __shfl_xor_sync(0xffffffffu, sum1, 2);
        l0 = l0 * cr0 + sum0;
        l1 = l1 * cr1 + sum1;
#pragma unroll
        for (int t = 0; t < 8; t++) {
            o[t][0] *= cr0; o[t][1] *= cr0;
            o[t][2] *= cr1; o[t][3] *= cr1;
        }
        m0 = mn0; m1 = mn1;

#pragma unroll
        for (int kk = 0; kk < 4; kk++) {
            uint32_t ph[4], pl[4];
            {
                __nv_bfloat16 hi0, lo0, hi1, lo1;
                split_bf16(s[2 * kk][0], hi0, lo0);
                split_bf16(s[2 * kk][1], hi1, lo1);
                ph[0] = pack_bf2(hi0, hi1);  pl[0] = pack_bf2(lo0, lo1);
                split_bf16(s[2 * kk][2], hi0, lo0);
                split_bf16(s[2 * kk][3], hi1, lo1);
                ph[1] = pack_bf2(hi0, hi1);  pl[1] = pack_bf2(lo0, lo1);
                split_bf16(s[2 * kk + 1][0], hi0, lo0);
                split_bf16(s[2 * kk + 1][1], hi1, lo1);
                ph[2] = pack_bf2(hi0, hi1);  pl[2] = pack_bf2(lo0, lo1);
                split_bf16(s[2 * kk + 1][2], hi0, lo0);
                split_bf16(s[2 * kk + 1][3], hi1, lo1);
                ph[3] = pack_bf2(hi0, hi1);  pl[3] = pack_bf2(lo0, lo1);
            }
            int kr = kk * 16 + vrow0;
#pragma unroll
            for (int cp = 0; cp < 4; cp++) {
                int chk = 2 * cp + vchkb;
                uint32_t addr = (uint32_t)(kr * 128) + (uint32_t)((chk ^ (kr & 7)) << 4);
                uint32_t bv[4];
                ldsm_x4_t(bv[0], bv[1], bv[2], bv[3], VHs + addr);
                mma16816(o[2 * cp],     ph, bv + 0);
                mma16816(o[2 * cp + 1], ph, bv + 2);
                mma16816(o[2 * cp],     pl, bv + 0);
                mma16816(o[2 * cp + 1], pl, bv + 2);
                ldsm_x4_t(bv[0], bv[1], bv[2], bv[3], VLs + addr);
                mma16816(o[2 * cp],     ph, bv + 0);
                mma16816(o[2 * cp + 1], ph, bv + 2);
            }
        }
        __syncthreads();
    }

    float i0 = 1.0f / l0, i1 = 1.0f / l1;
    int lr0 = q0 + wid * 16 + (lane >> 2);
    int lr1 = lr0 + 8;
    int col0 = h * KHD + 2 * (lane & 3);
#pragma unroll
    for (int t = 0; t < 8; t++) {
        int col = col0 + t * 8;
        if (lr0 < cnt)
            *(float2*)(Of + (size_t)(seg + lr0) * DDIM + col)
                = make_float2(o[t][0] * i0, o[t][1] * i0);
        if (lr1 < cnt)
            *(float2*)(Of + (size_t)(seg + lr1) * DDIM + col)
                = make_float2(o[t][2] * i1, o[t][3] * i1);
    }
}

// ===================== small fp32 GEMM: O[M,4] = A[M,K] @ B4[K,4] ===========
__global__ void k_mat4(const float* __restrict__ A, const float* __restrict__ B4,
                       float* __restrict__ O4, int K)
{
    int m = blockIdx.x * 8 + (threadIdx.x >> 5);
    int lane = threadIdx.x & 31;
    const float* ar = A + (size_t)m * K;
    float a0 = 0.f, a1 = 0.f, a2 = 0.f, a3 = 0.f;
    for (int k = lane; k < K; k += 32) {
        float a = ar[k];
        float4 b = *(const float4*)(B4 + (size_t)k * 4);
        a0 = fmaf(a, b.x, a0); a1 = fmaf(a, b.y, a1);
        a2 = fmaf(a, b.z, a2); a3 = fmaf(a, b.w, a3);
    }
#pragma unroll
    for (int off = 16; off; off >>= 1) {
        a0 += __shfl_down_sync(0xffffffffu, a0, off);
        a1 += __shfl_down_sync(0xffffffffu, a1, off);
        a2 += __shfl_down_sync(0xffffffffu, a2, off);
        a3 += __shfl_down_sync(0xffffffffu, a3, off);
    }
    if (lane == 0)
        *(float4*)(O4 + (size_t)m * 4) = make_float4(a0, a1, a2, a3);
}

// ===================== gate argmax (attbf @ c0, hi+lo reconstruct) ==========
__global__ void k_gate(const __nv_bfloat16* __restrict__ Hb, const float* __restrict__ Wg,
                       int* __restrict__ idx)
{
    int warp = (blockIdx.x * blockDim.x + threadIdx.x) >> 5;
    int lane = threadIdx.x & 31;
    if (warp >= MROWS) return;
    const __nv_bfloat16* hr = Hb + (size_t)warp * (2 * DDIM);
    float g[ENUM] = {0, 0, 0, 0};
    for (int d = lane; d < DDIM; d += 32) {
        float hv = __bfloat162float(hr[d]) + __bfloat162float(hr[DDIM + d]);
#pragma unroll
        for (int e = 0; e < ENUM; e++) g[e] = fmaf(hv, Wg[d * ENUM + e], g[e]);
    }
#pragma unroll
    for (int e = 0; e < ENUM; e++)
#pragma unroll
        for (int off = 16; off; off >>= 1)
            g[e] += __shfl_down_sync(0xffffffff, g[e], off);
    if (lane == 0) {
        int best = 0; float bv = g[0];
#pragma unroll
        for (int e = 1; e < ENUM; e++)
            if (g[e] > bv) { bv = g[e]; best = e; }
        idx[warp] = best;
    }
}

// ===================== compaction: scan / offsets / slot2tok ================
__global__ __launch_bounds__(1024)
void k_scan(const int* __restrict__ idx, int* __restrict__ pos, int* __restrict__ cnt)
{
    int e = blockIdx.x, b = blockIdx.y;
    int t = threadIdx.x;
    int token = b * SLEN + t;
    int p = (idx[token] == e) ? 1 : 0;
    int v = p;
#pragma unroll
    for (int o = 1; o < 32; o <<= 1) {
        int u = __shfl_up_sync(0xffffffffu, v, o);
        if ((t & 31) >= o) v += u;
    }
    __shared__ int wsum[32];
    if ((t & 31) == 31) wsum[t >> 5] = v;
    __syncthreads();
    if (t < 32) {
        int w = wsum[t];
#pragma unroll
        for (int o = 1; o < 32; o <<= 1) {
            int u = __shfl_up_sync(0xffffffffu, w, o);
            if (t >= o) w += u;
        }
        wsum[t] = w;
    }
    __syncthreads();
    int incl = v + ((t >= 32) ? wsum[(t >> 5) - 1] : 0);
    if (p) pos[token] = incl - 1;
    if (t == 1023) cnt[e * BNUM + b] = incl;
}

__global__ void k_off(const int* __restrict__ cnt, int* __restrict__ segoff,
                      int* __restrict__ ne)
{
    int e = threadIdx.x;
    if (e < ENUM) {
        int s = 0;
        for (int b = 0; b < BNUM; b++) { segoff[e * BNUM + b] = s; s += cnt[e * BNUM + b]; }
        ne[e] = s;
    }
}

__global__ void k_s2t(const int* __restrict__ idx, const int* __restrict__ pos,
                      const int* __restrict__ segoff, int* __restrict__ s2t)
{
    int t = blockIdx.x * blockDim.x + threadIdx.x;
    int e = idx[t], b = t / SLEN;
    s2t[(size_t)e * MROWS + segoff[e * BNUM + b] + pos[t]] = t;
}

// ===================== mean-v rows (from split qkv, fp32 out) ===============
__global__ __launch_bounds__(512)
void k_meanv(const __nv_bfloat16* __restrict__ qkvcbf, const int* __restrict__ cnt32,
             const int* __restrict__ seg32, const int* __restrict__ ne,
             float* __restrict__ cattf)
{
    __shared__ float4 part[4][128];
    int b = blockIdx.x, e = blockIdx.y;
    int cnt = __ldg(cnt32 + e * BNUM + b), seg = __ldg(seg32 + e * BNUM + b);
    const __nv_bfloat16* QKV = qkvcbf + (size_t)e * MROWS * (2 * QKVW);
    int c4 = threadIdx.x & 127, rg = threadIdx.x >> 7;
    int c = c4 * 4;
    float4 s = make_float4(0.f, 0.f, 0.f, 0.f);
    for (int r = rg; r < cnt; r += 4) {
        const __nv_bfloat16* row = QKV + (size_t)(seg + r) * (2 * QKVW);
        uint64_t uh = *(const uint64_t*)(row + 2 * DDIM + c);
        uint64_t ul = *(const uint64_t*)(row + QKVW + 2 * DDIM + c);
        const __nv_bfloat16* ph = (const __nv_bfloat16*)&uh;
        const __nv_bfloat16* pl = (const __nv_bfloat16*)&ul;
        s.x += __bfloat162float(ph[0]) + __bfloat162float(pl[0]);
        s.y += __bfloat162float(ph[1]) + __bfloat162float(pl[1]);
        s.z += __bfloat162float(ph[2]) + __bfloat162float(pl[2]);
        s.w += __bfloat162float(ph[3]) + __bfloat162float(pl[3]);
    }
    part[rg][c4] = s;
    __syncthreads();
    if (rg == 0) {
        float4 p1 = part[1][c4], p2 = part[2][c4], p3 = part[3][c4];
        s.x += p1.x + p2.x + p3.x;
        s.y += p1.y + p2.y + p3.y;
        s.z += p1.z + p2.z + p3.z;
        s.w += p1.w + p2.w + p3.w;
        const float is = 1.0f / (float)SLEN;
        int target = __ldg(ne + e) + b;
        float* row = cattf + ((size_t)e * CROWS + target) * DDIM + c;
        row[0] = s.x * is; row[1] = s.y * is;
        row[2] = s.z * is; row[3] = s.w * is;
    }
}

// ===================== mean scalars (catt mean rows . v0) ===================
__global__ __launch_bounds__(1024)
void k_msum2(const float* __restrict__ cattf, const int* __restrict__ ne,
             const float* __restrict__ v0,
             float* __restrict__ meanS, float* __restrict__ totalS)
{
    __shared__ float sh[ENUM * BNUM];
    int w = threadIdx.x >> 5, lane = threadIdx.x & 31;
    int e = w >> 3, b = w & 7;
    const float* row = cattf + ((size_t)e * CROWS + __ldg(ne + e) + b) * DDIM;
    const float* vv = v0 + e * DDIM;
    float s = 0.0f;
    for (int d = lane; d < DDIM; d += 32) s = fmaf(row[d], vv[d], s);
#pragma unroll
    for (int off = 16; off; off >>= 1) s += __shfl_down_sync(0xffffffff, s, off);
    if (lane == 0) { sh[w] = s; meanS[w] = s; }
    __syncthreads();
    if (threadIdx.x < BNUM) {
        float t = 0.0f;
        for (int e2 = 0; e2 < ENUM; e2++) t += sh[e2 * BNUM + threadIdx.x];
        totalS[threadIdx.x] = t;
    }
}

// ===================== final: catt . v0 + mean corrections ==================
__global__ void k_final3(const float* __restrict__ cattf, const int* __restrict__ idx,
                         const int* __restrict__ pos, const int* __restrict__ segoff,
                         const float* __restrict__ v0, const float* __restrict__ meanS,
                         const float* __restrict__ totalS, float* __restrict__ out)
{
    int warp = (blockIdx.x * blockDim.x + threadIdx.x) >> 5;
    int lane = threadIdx.x & 31;
    if (warp >= MROWS) return;
    int e = idx[warp], b = warp / SLEN;
    int slot = segoff[e * BNUM + b] + pos[warp];
    const float* r = cattf + ((size_t)e * CROWS + slot) * DDIM;
    const float* vv = v0 + e * DDIM;
    float s = 0.0f;
    for (int d = lane; d < DDIM; d += 32) s = fmaf(r[d], vv[d], s);
#pragma unroll
    for (int off = 16; off; off >>= 1) s += __shfl_down_sync(0xffffffff, s, off);
    if (lane == 0) out[warp] = s + totalS[b] - meanS[e * BNUM + b];
}

// ===================== host orchestration ===================================
extern "C" void kernel_launch(void* const* d_in, const int* in_sizes, int n_in,
                              void* d_out, int out_size)
{
    (void)in_sizes; (void)n_in; (void)out_size;
    const int*   tokens = (const int*)  d_in[0];
    const float* emb    = (const float*)d_in[1];
    const float* Wq     = (const float*)d_in[2];
    const float* Wk     = (const float*)d_in[3];
    const float* Wv     = (const float*)d_in[4];
    const float* Wo     = (const float*)d_in[5];
    const float* W1     = (const float*)d_in[6];
    const float* W2     = (const float*)d_in[7];
    const float* Wg     = (const float*)d_in[8];
    const float* eWq    = (const float*)d_in[9];
    const float* eWk    = (const float*)d_in[10];
    const float* eWv    = (const float*)d_in[11];
    const float* eWo    = (const float*)d_in[12];
    const float* eW1    = (const float*)d_in[13];
    const float* eW2    = (const float*)d_in[14];
    const float* Wout   = (const float*)d_in[15];
    float* out = (float*)d_out;

    __nv_bfloat16 *xbf, *qkvbf, *attbf, *qkvcbf;
    __nv_bfloat16 *swqkv, *sw1, *sw2, *swoA, *scmb1, *cmbA, *ewqkv, *ecmbQKV;
    float *catt, *meanS, *totalS, *c2, *c1, *c0, *v2, *v1, *v0;
    int *idx, *cnt, *segoff, *ne, *pos, *s2t;
    cudaGetSymbolAddress((void**)&xbf,     g_xbf);
    cudaGetSymbolAddress((void**)&qkvbf,   g_qkvbf);
    cudaGetSymbolAddress((void**)&attbf,   g_attbf);
    cudaGetSymbolAddress((void**)&idx,     g_idx);
    cudaGetSymbolAddress((void**)&cnt,     g_cnt);
    cudaGetSymbolAddress((void**)&segoff,  g_segoff);
    cudaGetSymbolAddress((void**)&ne,      g_ne);
    cudaGetSymbolAddress((void**)&pos,     g_pos);
    cudaGetSymbolAddress((void**)&s2t,     g_s2t);
    cudaGetSymbolAddress((void**)&meanS,   g_meanS);
    cudaGetSymbolAddress((void**)&totalS,  g_totalS);
    cudaGetSymbolAddress((void**)&c2,      g_c2);
    cudaGetSymbolAddress((void**)&c1,      g_c1);
    cudaGetSymbolAddress((void**)&c0,      g_c0);
    cudaGetSymbolAddress((void**)&v2,      g_v2);
    cudaGetSymbolAddress((void**)&v1,      g_v1);
    cudaGetSymbolAddress((void**)&v0,      g_v0);
    cudaGetSymbolAddress((void**)&qkvcbf,  g_qkvcbf);
    cudaGetSymbolAddress((void**)&catt,    g_catt);
    cudaGetSymbolAddress((void**)&swqkv,   g_swqkv);
    cudaGetSymbolAddress((void**)&sw1,     g_sw1);
    cudaGetSymbolAddress((void**)&sw2,     g_sw2);
    cudaGetSymbolAddress((void**)&swoA,    g_swoA);
    cudaGetSymbolAddress((void**)&scmb1,   g_scmb1);
    cudaGetSymbolAddress((void**)&cmbA,    g_cmbA);
    cudaGetSymbolAddress((void**)&ewqkv,   g_ewqkv);
    cudaGetSymbolAddress((void**)&ecmbQKV, g_ecmbQKV);

    cudaFuncSetAttribute(k_gemm3, cudaFuncAttributeMaxDynamicSharedMemorySize, G3_SMEM);
    cudaFuncSetAttribute(k_attn_mma, cudaFuncAttributeMaxDynamicSharedMemorySize, ATT_SMEM);
    cudaFuncSetAttribute(k_attn_mma_c, cudaFuncAttributeMaxDynamicSharedMemorySize, ATT_SMEM);

    static cudaStream_t s_side = nullptr;
    static cudaEvent_t  s_evFork = nullptr, s_evC0 = nullptr,
                        s_evExp = nullptr, s_evV = nullptr;
    if (!s_side) {
        cudaStreamCreateWithFlags(&s_side, cudaStreamNonBlocking);
        cudaEventCreateWithFlags(&s_evFork, cudaEventDisableTiming);
        cudaEventCreateWithFlags(&s_evC0,   cudaEventDisableTiming);
        cudaEventCreateWithFlags(&s_evExp,  cudaEventDisableTiming);
        cudaEventCreateWithFlags(&s_evV,    cudaEventDisableTiming);
    }

    dim3 tb32(32, 8);
    const size_t WQKV_SZ = (size_t)QKVW * 2 * DDIM;

    // ======== fork: side stream = all weight prep ========
    cudaEventRecord(s_evFork, 0);
    cudaStreamWaitEvent(s_side, s_evFork, 0);

    // side: exact fp32 gate combo c0 (needed first, at gate)
    k_mat4<<<FFD / 8, 256, 0, s_side>>>(W2, Wg, c2, DDIM);
    k_mat4<<<DDIM / 8, 256, 0, s_side>>>(W1, c2, c1, FFD);
    k_mat4<<<DDIM / 8, 256, 0, s_side>>>(Wo, c1, c0, DDIM);
    cudaEventRecord(s_evC0, s_side);

    // side: shared FFN weights -> cmbA = (Wo@W1@W2) row-major split
    k_cvt_wt<<<dim3(FFD / 32, DDIM / 32, 1), tb32, 0, s_side>>>(W1, 0, sw1, 0, DDIM, FFD);
    k_cvt_wt<<<dim3(DDIM / 32, FFD / 32, 1), tb32, 0, s_side>>>(W2, 0, sw2, 0, FFD, DDIM);
    k_cvt_a<<<dim3(256, 1, 1), 256, 0, s_side>>>(Wo, 0, swoA, 0);
    k_gemm3<<<dim3(FFD / 128, 4, 1), 256, G3_SMEM, s_side>>>(
        swoA, 0, sw1, 0, nullptr, 0, scmb1, 0, FFD, DDIM, nullptr, DDIM, 0, nullptr);
    k_gemm3<<<dim3(DDIM / 128, 4, 1), 256, G3_SMEM, s_side>>>(
        scmb1, 0, sw2, 0, nullptr, 0, cmbA, 0, DDIM, FFD, nullptr, DDIM, 0, nullptr);

    // side: expert qkv weights + combined (cmb @ eWqkv)^T
    k_cvt_qkv<<<dim3(DDIM / 32, DDIM / 32, 3 * ENUM), tb32, 0, s_side>>>(
        eWq, eWk, eWv, (size_t)DDIM * DDIM, ewqkv, WQKV_SZ);
    k_gemm3<<<dim3(DDIM / 128, QKVW / 128, ENUM), 256, G3_SMEM, s_side>>>(
        ewqkv, WQKV_SZ, cmbA, 0, nullptr, 0, ecmbQKV, WQKV_SZ,
        DDIM, DDIM, nullptr, QKVW, 0, nullptr);
    cudaEventRecord(s_evExp, s_side);

    // side: exact fp32 expert out-vector v0 = eWo@(eW1@(eW2@Wout))
    k_matv<<<dim3(FFD / 8, 1, ENUM), 256, 0, s_side>>>(
        eW2, (size_t)FFD * DDIM, Wout, 0, v2, FFD, DDIM);
    k_matv<<<dim3(DDIM / 8, 1, ENUM), 256, 0, s_side>>>(
        eW1, (size_t)DDIM * FFD, v2, FFD, v1, DDIM, FFD);
    k_matv<<<dim3(DDIM / 8, 1, ENUM), 256, 0, s_side>>>(
        eWo, (size_t)DDIM * DDIM, v1, DDIM, v0, DDIM, DDIM);
    cudaEventRecord(s_evV, s_side);

    // ======== main stream: shared block + gate ========
    k_cvt_qkv<<<dim3(DDIM / 32, DDIM / 32, 3), tb32>>>(Wq, Wk, Wv, 0, swqkv, 0);
    k_gather<<<(MROWS * (DDIM / 4)) / 256, 256>>>(tokens, emb, xbf);
    k_gemm3<<<dim3(QKVW / 128, MROWS / 128, 1), 256, G3_SMEM>>>(
        xbf, 0, swqkv, 0, nullptr, 0, qkvbf, 0, QKVW, DDIM, nullptr, MROWS, 0, nullptr);
    k_attn_mma<<<dim3(SLEN / 128, BNUM * HNUM), 256, ATT_SMEM>>>(qkvbf, attbf);

    cudaStreamWaitEvent(0, s_evC0, 0);
    k_gate<<<MROWS / 8, 256>>>(attbf, c0, idx);
    k_scan<<<dim3(ENUM, BNUM), 1024>>>(idx, pos, cnt);
    k_off<<<1, 32>>>(cnt, segoff, ne);
    k_s2t<<<MROWS / 256, 256>>>(idx, pos, segoff, s2t);

    // ======== experts: gathered-A qkv GEMM with combined weights ========
    cudaStreamWaitEvent(0, s_evExp, 0);
    k_gemm3<<<dim3(QKVW / 128, MROWS / 128, ENUM), 256, G3_SMEM>>>(
        attbf, 0, ecmbQKV, WQKV_SZ,
        nullptr, 0, qkvcbf, (size_t)MROWS * 2 * QKVW, QKVW, DDIM, ne, 0, 0, s2t);
    k_attn_mma_c<<<dim3(SLEN / 128, BNUM * HNUM, ENUM), 256, ATT_SMEM>>>(
        qkvcbf, catt, cnt, segoff);
    k_meanv<<<dim3(BNUM, ENUM), 512>>>(qkvcbf, cnt, segoff, ne, catt);

    // ---- mean scalars + final assembly ----
    cudaStreamWaitEvent(0, s_evV, 0);
    k_msum2<<<1, 1024>>>(catt, ne, v0, meanS, totalS);
    k_final3<<<MROWS / 8, 256>>>(catt, idx, pos, segoff, v0, meanS, totalS, out);
}

// round 15
// speedup vs baseline: 1.0608x; 1.0608x over previous
#include <cuda_runtime.h>
#include <cuda_bf16.h>
#include <math.h>
#include <stdint.h>

// Problem constants
#define MROWS 8192      // B*S
#define DDIM  512
#define HNUM  8
#define KHD   64
#define FFD   2048
#define ENUM  4
#define SLEN  1024
#define BNUM  8
#define QKVW  1536
#define CROWS (MROWS + 128)   // compact rows + mean-row margin

// ===================== scratch (device globals) ==============================
__device__ __nv_bfloat16 g_xbf  [MROWS * 2 * DDIM];     // embedding, split
__device__ __nv_bfloat16 g_qkvbf[MROWS * 2 * QKVW];     // shared qkv, split
__device__ __nv_bfloat16 g_attbf[MROWS * 2 * DDIM];     // shared attn out split
__device__ int   g_idx[MROWS];
__device__ int   g_cnt[ENUM * BNUM];
__device__ int   g_segoff[ENUM * BNUM];
__device__ int   g_ne[ENUM];
__device__ int   g_pos[MROWS];
__device__ float g_meanS[ENUM * BNUM];
__device__ float g_totalS[BNUM];
__device__ float g_c2[FFD * ENUM];                       // W2@Wg
__device__ float g_c1[DDIM * ENUM];                      // W1@c2
__device__ float g_c0[DDIM * ENUM];                      // Wo@c1 (gate matrix)
__device__ float g_v2[ENUM * FFD];                       // eW2@Wout
__device__ float g_v1[ENUM * DDIM];                      // eW1@v2
__device__ float g_v0[ENUM * DDIM];                      // eWo@v1 (expert out vector)
__device__ __align__(16) unsigned char g_zerobuf[16];

// per-expert compact buffers
__device__ __nv_bfloat16 g_cbfA  [ENUM * MROWS * 2 * DDIM];  // scattered h split
__device__ __nv_bfloat16 g_qkvcbf[ENUM * MROWS * 2 * QKVW];  // compact qkv split
__device__ float         g_catt  [ENUM * CROWS * DDIM];      // compact attn + mean rows

// weights: bf16 hi|lo split. *_T = transposed [N, 2K]; *_A = row-split [M, 2K]
__device__ __nv_bfloat16 g_swqkv[QKVW * 2 * DDIM];
__device__ __nv_bfloat16 g_sw1  [FFD  * 2 * DDIM];
__device__ __nv_bfloat16 g_sw2  [DDIM * 2 * FFD];
__device__ __nv_bfloat16 g_swoA [DDIM * 2 * DDIM];
__device__ __nv_bfloat16 g_scmb1[DDIM * 2 * FFD];        // Wo@W1 split
__device__ __nv_bfloat16 g_scmbB[DDIM * 2 * DDIM];       // (Wo@W1@W2)^T-format
__device__ __nv_bfloat16 g_ewqkv[ENUM * QKVW * 2 * DDIM];

// ===================== PTX helpers (base ISA only) ==========================
__device__ __forceinline__ uint32_t smem_u32(const void* p) {
    uint32_t a;
    asm("{ .reg .u64 t; cvta.to.shared.u64 t, %1; cvt.u32.u64 %0, t; }"
        : "=r"(a) : "l"(p));
    return a;
}
__device__ __forceinline__ void cp16(uint32_t dst, const void* src) {
    asm volatile("cp.async.cg.shared.global [%0], [%1], 16;"
                 :: "r"(dst), "l"(src) : "memory");
}
__device__ __forceinline__ void ldsm_x4(uint32_t& r0, uint32_t& r1,
                                        uint32_t& r2, uint32_t& r3, uint32_t addr) {
    asm volatile("ldmatrix.sync.aligned.m8n8.x4.shared.b16 {%0,%1,%2,%3}, [%4];"
                 : "=r"(r0), "=r"(r1), "=r"(r2), "=r"(r3) : "r"(addr));
}
__device__ __forceinline__ void ldsm_x4_t(uint32_t& r0, uint32_t& r1,
                                          uint32_t& r2, uint32_t& r3, uint32_t addr) {
    asm volatile("ldmatrix.sync.aligned.m8n8.x4.trans.shared.b16 {%0,%1,%2,%3}, [%4];"
                 : "=r"(r0), "=r"(r1), "=r"(r2), "=r"(r3) : "r"(addr));
}
__device__ __forceinline__ void mma16816(float* c, const uint32_t* a, const uint32_t* b) {
    asm volatile("mma.sync.aligned.m16n8k16.row.col.f32.bf16.bf16.f32 "
                 "{%0,%1,%2,%3}, {%4,%5,%6,%7}, {%8,%9}, {%0,%1,%2,%3};"
                 : "+f"(c[0]), "+f"(c[1]), "+f"(c[2]), "+f"(c[3])
                 : "r"(a[0]), "r"(a[1]), "r"(a[2]), "r"(a[3]),
                   "r"(b[0]), "r"(b[1]));
}
__device__ __forceinline__ void split_bf16(float x, __nv_bfloat16& hi, __nv_bfloat16& lo) {
    hi = __float2bfloat16(x);
    lo = __float2bfloat16(x - __bfloat162float(hi));
}
__device__ __forceinline__ uint32_t pack_bf2(__nv_bfloat16 a, __nv_bfloat16 b) {
    __nv_bfloat162 t = __halves2bfloat162(a, b);
    return *(uint32_t*)&t;
}

// ===================== embedding gather (split output) ======================
__global__ void k_gather(const int* __restrict__ tok,
                         const float* __restrict__ emb,
                         __nv_bfloat16* __restrict__ xbf)
{
    int t  = blockIdx.x * blockDim.x + threadIdx.x;
    int i  = t >> 7;
    int c4 = t & 127;
    float4 v = ((const float4*)(emb + (size_t)tok[i] * DDIM))[c4];
    float xv[4] = {v.x, v.y, v.z, v.w};
    __nv_bfloat16 hi[4], lo[4];
#pragma unroll
    for (int j = 0; j < 4; j++) split_bf16(xv[j], hi[j], lo[j]);
    __nv_bfloat16* row = xbf + (size_t)i * (2 * DDIM);
    *(uint64_t*)(row + c4 * 4)        = *(uint64_t*)hi;
    *(uint64_t*)(row + DDIM + c4 * 4) = *(uint64_t*)lo;
}

// ===================== weight conversion kernels ============================
__global__ void k_cvt_wt(const float* __restrict__ W, size_t wSz,
                         __nv_bfloat16* __restrict__ Y, size_t ySz,
                         int K, int N)
{
    W += (size_t)blockIdx.z * wSz;
    Y += (size_t)blockIdx.z * ySz;
    __shared__ float tile[32][33];
    int k0 = blockIdx.y * 32, n0 = blockIdx.x * 32;
    int tx = threadIdx.x, ty = threadIdx.y;   // 32 x 8
#pragma unroll
    for (int i = 0; i < 32; i += 8)
        tile[ty + i][tx] = W[(size_t)(k0 + ty + i) * N + n0 + tx];
    __syncthreads();
#pragma unroll
    for (int i = 0; i < 32; i += 8) {
        float x = tile[tx][ty + i];
        __nv_bfloat16 hi, lo; split_bf16(x, hi, lo);
        size_t base = (size_t)(n0 + ty + i) * (2 * K) + k0 + tx;
        Y[base]     = hi;
        Y[base + K] = lo;
    }
}

__global__ void k_cvt_qkv(const float* __restrict__ Wq_, const float* __restrict__ Wk_,
                          const float* __restrict__ Wv_, size_t wSz,
                          __nv_bfloat16* __restrict__ Y, size_t ySz)
{
    int e = blockIdx.z / 3, which = blockIdx.z % 3;
    const float* W = (which == 0) ? Wq_ : (which == 1) ? Wk_ : Wv_;
    W += (size_t)e * wSz;
    __nv_bfloat16* Yp = Y + (size_t)e * ySz + (size_t)which * (DDIM * 2 * DDIM);
    __shared__ float tile[32][33];
    int k0 = blockIdx.y * 32, n0 = blockIdx.x * 32;
    int tx = threadIdx.x, ty = threadIdx.y;
#pragma unroll
    for (int i = 0; i < 32; i += 8)
        tile[ty + i][tx] = W[(size_t)(k0 + ty + i) * DDIM + n0 + tx];
    __syncthreads();
#pragma unroll
    for (int i = 0; i < 32; i += 8) {
        float x = tile[tx][ty + i];
        __nv_bfloat16 hi, lo; split_bf16(x, hi, lo);
        size_t base = (size_t)(n0 + ty + i) * (2 * DDIM) + k0 + tx;
        Yp[base]        = hi;
        Yp[base + DDIM] = lo;
    }
}

__global__ void k_cvt_a(const float* __restrict__ W, size_t wSz,
                        __nv_bfloat16* __restrict__ Y, size_t ySz)
{
    W += (size_t)blockIdx.z * wSz;
    Y += (size_t)blockIdx.z * ySz;
    int t  = blockIdx.x * blockDim.x + threadIdx.x;
    int r  = t >> 7;
    int c4 = t & 127;
    float4 v = ((const float4*)(W + (size_t)r * DDIM))[c4];
    float xv[4] = {v.x, v.y, v.z, v.w};
    __nv_bfloat16 hi[4], lo[4];
#pragma unroll
    for (int j = 0; j < 4; j++) split_bf16(xv[j], hi[j], lo[j]);
    __nv_bfloat16* row = Y + (size_t)r * (2 * DDIM);
    *(uint64_t*)(row + c4 * 4)        = *(uint64_t*)hi;
    *(uint64_t*)(row + DDIM + c4 * 4) = *(uint64_t*)lo;
}

// ===================== fp32 matvec: o[r] = W[r,:] . v (z-batched) ===========
__global__ void k_matv(const float* __restrict__ W, size_t wSz,
                       const float* __restrict__ v, size_t vSz,
                       float* __restrict__ o, size_t oSz, int K)
{
    W += (size_t)blockIdx.z * wSz;
    v += (size_t)blockIdx.z * vSz;
    o += (size_t)blockIdx.z * oSz;
    int r = blockIdx.x * 8 + (threadIdx.x >> 5);
    int lane = threadIdx.x & 31;
    const float* wr = W + (size_t)r * K;
    float s = 0.0f;
    for (int k = lane; k < K; k += 32) s = fmaf(wr[k], v[k], s);
#pragma unroll
    for (int off = 16; off; off >>= 1) s += __shfl_down_sync(0xffffffffu, s, off);
    if (lane == 0) o[r] = s;
}

// ===================== mma.sync bf16x3 GEMM — fused 3-product ===============
// Optional scatter epilogue: when Y && sidx, output row i goes to
// Y[((idx[i]*MROWS)+segoff[idx[i]*8+(i>>10)]+pos[i]) * 2N] as split bf16.
#define G3_STAGE 32768
#define G3_SMEM  (3 * G3_STAGE)

__global__ __launch_bounds__(256, 2)
void k_gemm3(const __nv_bfloat16* __restrict__ Ag, size_t aSz,
             const __nv_bfloat16* __restrict__ Bg, size_t bSz,
             float* __restrict__ Cf, size_t cSz,
             __nv_bfloat16* __restrict__ Y, size_t ySz,
             int N, int K,
             const int* __restrict__ nptr, int nconst, int nadd,
             const int* __restrict__ sidx, const int* __restrict__ spos,
             const int* __restrict__ sseg)
{
    const int z = blockIdx.z;
    Ag += (size_t)z * aSz;
    Bg += (size_t)z * bSz;
    const int n = (nptr ? __ldg(nptr + z) : nconst) + nadd;
    const int mbase = blockIdx.y * 128;
    if (mbase >= n) return;
    if (Cf) Cf += (size_t)z * cSz;
    if (Y && !sidx) Y += (size_t)z * ySz;

    extern __shared__ __align__(128) unsigned char smem[];
    const uint32_t sbase = smem_u32(smem);
    const int tid  = threadIdx.x;
    const int wid  = tid >> 5;
    const int lane = tid & 31;

    const int nbase = blockIdx.x * 128;
    const int K2    = 2 * K;
    const int NCP   = K / 32;

    const int mo = (wid >> 2) * 64;
    const int no = (wid & 3) * 32;

    auto fill = [&](int c) {
        int s   = c % 3;
        int col = c * 32;
        uint32_t base = sbase + s * G3_STAGE;
#pragma unroll
        for (int i2 = 0; i2 < 2; i2++) {
            int ch = tid + i2 * 256;
            int r  = ch >> 2, cc = ch & 3;
            uint32_t off = (uint32_t)(r * 64) + (uint32_t)((cc ^ ((r >> 1) & 3)) << 4);
            const __nv_bfloat16* arow = Ag + (size_t)(mbase + r) * K2 + col + cc * 8;
            bool act = (mbase + r) < n;
            cp16(base + off, act ? (const void*)arow : (const void*)g_zerobuf);
            cp16(base + 8192 + off, act ? (const void*)(arow + K) : (const void*)g_zerobuf);
            const __nv_bfloat16* brow = Bg + (size_t)(nbase + r) * K2 + col + cc * 8;
            cp16(base + 16384 + off, brow);
            cp16(base + 24576 + off, brow + K);
        }
        asm volatile("cp.async.commit_group;" ::: "memory");
    };

    float acc[4][4][4];
#pragma unroll
    for (int i = 0; i < 4; i++)
#pragma unroll
        for (int j = 0; j < 4; j++)
#pragma unroll
            for (int t = 0; t < 4; t++) acc[i][j][t] = 0.0f;

    fill(0);
    if (NCP > 1) fill(1);

    for (int c = 0; c < NCP; c++) {
        if (c + 1 < NCP) asm volatile("cp.async.wait_group 1;" ::: "memory");
        else             asm volatile("cp.async.wait_group 0;" ::: "memory");
        __syncthreads();

        if (c + 2 < NCP) fill(c + 2);

        uint32_t sA = sbase + (c % 3) * G3_STAGE;
        uint32_t sB = sA + 16384;

#pragma unroll
        for (int kk = 0; kk < 2; kk++) {
            uint32_t a[4][4];
            uint32_t b[4][2];
            int achk = 2 * kk + (lane >> 4);
            int arow0 = lane & 15;
            int bchk = 2 * kk + ((lane >> 3) & 1);
            int brow0 = (lane & 7) + ((lane >> 4) << 3);

#pragma unroll
            for (int i = 0; i < 4; i++) {
                int row = mo + i * 16 + arow0;
                ldsm_x4(a[i][0], a[i][1], a[i][2], a[i][3],
                        sA + row * 64 + (uint32_t)(((achk ^ ((row >> 1) & 3))) << 4));
            }
#pragma unroll
            for (int jj = 0; jj < 2; jj++) {
                int nrow = no + jj * 16 + brow0;
                ldsm_x4(b[2 * jj][0], b[2 * jj][1], b[2 * jj + 1][0], b[2 * jj + 1][1],
                        sB + nrow * 64 + (uint32_t)(((bchk ^ ((nrow >> 1) & 3))) << 4));
            }
#pragma unroll
            for (int i = 0; i < 4; i++)
#pragma unroll
                for (int j = 0; j < 4; j++)
                    mma16816(acc[i][j], a[i], b[j]);

#pragma unroll
            for (int i = 0; i < 4; i++) {
                int row = mo + i * 16 + arow0;
                ldsm_x4(a[i][0], a[i][1], a[i][2], a[i][3],
                        sA + 8192 + row * 64 + (uint32_t)(((achk ^ ((row >> 1) & 3))) << 4));
            }
#pragma unroll
            for (int i = 0; i < 4; i++)
#pragma unroll
                for (int j = 0; j < 4; j++)
                    mma16816(acc[i][j], a[i], b[j]);

#pragma unroll
            for (int i = 0; i < 4; i++) {
                int row = mo + i * 16 + arow0;
                ldsm_x4(a[i][0], a[i][1], a[i][2], a[i][3],
                        sA + row * 64 + (uint32_t)(((achk ^ ((row >> 1) & 3))) << 4));
            }
#pragma unroll
            for (int jj = 0; jj < 2; jj++) {
                int nrow = no + jj * 16 + brow0;
                ldsm_x4(b[2 * jj][0], b[2 * jj][1], b[2 * jj + 1][0], b[2 * jj + 1][1],
                        sA + 24576 + nrow * 64 + (uint32_t)(((bchk ^ ((nrow >> 1) & 3))) << 4));
            }
#pragma unroll
            for (int i = 0; i < 4; i++)
#pragma unroll
                for (int j = 0; j < 4; j++)
                    mma16816(acc[i][j], a[i], b[j]);
        }
    }

    int rbase = mbase + mo + (lane >> 2);
    int cbase = nbase + no + (lane & 3) * 2;
#pragma unroll
    for (int i = 0; i < 4; i++) {
        int r0 = rbase + i * 16, r1 = r0 + 8;
        size_t y0 = 0, y1 = 0;
        if (Y) {
            if (sidx) {
                if (r0 < n) {
                    int e0 = __ldg(sidx + r0);
                    y0 = ((size_t)e0 * MROWS
                          + __ldg(sseg + e0 * BNUM + (r0 >> 10)) + __ldg(spos + r0));
                }
                if (r1 < n) {
                    int e1 = __ldg(sidx + r1);
                    y1 = ((size_t)e1 * MROWS
                          + __ldg(sseg + e1 * BNUM + (r1 >> 10)) + __ldg(spos + r1));
                }
            } else { y0 = (size_t)r0; y1 = (size_t)r1; }
        }
#pragma unroll
        for (int j = 0; j < 4; j++) {
            int col = cbase + j * 8;
            if (Cf) {
                if (r0 < n)
                    *(float2*)(Cf + (size_t)r0 * N + col) = make_float2(acc[i][j][0], acc[i][j][1]);
                if (r1 < n)
                    *(float2*)(Cf + (size_t)r1 * N + col) = make_float2(acc[i][j][2], acc[i][j][3]);
            }
            if (Y) {
                if (r0 < n) {
                    __nv_bfloat16 h0, l0, h1, l1;
                    split_bf16(acc[i][j][0], h0, l0);
                    split_bf16(acc[i][j][1], h1, l1);
                    *(__nv_bfloat162*)(Y + y0 * 2 * N + col)     = __halves2bfloat162(h0, h1);
                    *(__nv_bfloat162*)(Y + y0 * 2 * N + N + col) = __halves2bfloat162(l0, l1);
                }
                if (r1 < n) {
                    __nv_bfloat16 h0, l0, h1, l1;
                    split_bf16(acc[i][j][2], h0, l0);
                    split_bf16(acc[i][j][3], h1, l1);
                    *(__nv_bfloat162*)(Y + y1 * 2 * N + col)     = __halves2bfloat162(h0, h1);
                    *(__nv_bfloat162*)(Y + y1 * 2 * N + N + col) = __halves2bfloat162(l0, l1);
                }
            }
        }
    }
}

// ===================== MMA flash attention (shared block) ===================
#define ATT_SMEM 98304   // Q 32KB + 2 x (K/V hi/lo 32KB)

__global__ __launch_bounds__(256)
void k_attn_mma(const __nv_bfloat16* __restrict__ QKVs,
                __nv_bfloat16* __restrict__ Oy)
{
    extern __shared__ __align__(128) unsigned char smem[];
    const uint32_t sb = smem_u32(smem);
    const int tid = threadIdx.x, wid = tid >> 5, lane = tid & 31;
    const int bh = blockIdx.y, b = bh >> 3, h = bh & 7;
    const int q0 = blockIdx.x * 128;

    const uint32_t QH = sb, QL = sb + 16384;

#pragma unroll
    for (int i = 0; i < 8; i++) {
        int id = tid + i * 256;
        int half = id >> 10, rem = id & 1023;
        int qr = rem >> 3, c = rem & 7;
        const __nv_bfloat16* src = QKVs
            + (size_t)(b * SLEN + q0 + qr) * (2 * QKVW)
            + (size_t)half * QKVW + h * KHD + c * 8;
        cp16((half ? QL : QH) + qr * 128 + (uint32_t)((c ^ (qr & 7)) << 4), src);
    }
    asm volatile("cp.async.commit_group;" ::: "memory");

    auto fillkv = [&](int kc) {
        uint32_t base = sb + 32768 + (uint32_t)(kc & 1) * 32768;
#pragma unroll
        for (int i = 0; i < 8; i++) {
            int id = tid + i * 256;
            int sub = id >> 9, rem = id & 511;
            int kr = rem >> 3, c = rem & 7;
            int col = (sub == 0) ? (DDIM + h * KHD)
                    : (sub == 1) ? (QKVW + DDIM + h * KHD)
                    : (sub == 2) ? (2 * DDIM + h * KHD)
                                 : (QKVW + 2 * DDIM + h * KHD);
            const __nv_bfloat16* src = QKVs
                + (size_t)(b * SLEN + kc * 64 + kr) * (2 * QKVW) + col + c * 8;
            cp16(base + sub * 8192 + kr * 128 + (uint32_t)((c ^ (kr & 7)) << 4), src);
        }
        asm volatile("cp.async.commit_group;" ::: "memory");
    };

    fillkv(0);
    asm volatile("cp.async.wait_group 0;" ::: "memory");
    __syncthreads();

    uint32_t qh[4][4], ql[4][4];
    {
        int arow = wid * 16 + (lane & 15);
        int cb = lane >> 4;
#pragma unroll
        for (int kk = 0; kk < 4; kk++) {
            int chk = 2 * kk + cb;
            uint32_t off = (uint32_t)(arow * 128) + (uint32_t)((chk ^ (arow & 7)) << 4);
            ldsm_x4(qh[kk][0], qh[kk][1], qh[kk][2], qh[kk][3], QH + off);
            ldsm_x4(ql[kk][0], ql[kk][1], ql[kk][2], ql[kk][3], QL + off);
        }
    }

    float o[8][4];
#pragma unroll
    for (int t = 0; t < 8; t++)
#pragma unroll
        for (int i = 0; i < 4; i++) o[t][i] = 0.0f;
    float m0 = -INFINITY, m1 = -INFINITY, l0 = 0.0f, l1 = 0.0f;

    const int krow0 = (lane & 7) + ((lane >> 4) << 3);
    const int kchkb = (lane >> 3) & 1;
    const int vrow0 = lane & 15;
    const int vchkb = lane >> 4;

    for (int kc = 0; kc < 16; kc++) {
        if (kc) {
            asm volatile("cp.async.wait_group 0;" ::: "memory");
            __syncthreads();
        }
        if (kc + 1 < 16) fillkv(kc + 1);

        uint32_t KB  = sb + 32768 + (uint32_t)(kc & 1) * 32768;
        uint32_t KHs = KB, KLs = KB + 8192, VHs = KB + 16384, VLs = KB + 24576;

        float s[8][4];
#pragma unroll
        for (int t = 0; t < 8; t++)
#pragma unroll
            for (int i = 0; i < 4; i++) s[t][i] = 0.0f;

#pragma unroll
        for (int kk = 0; kk < 4; kk++) {
#pragma unroll
            for (int jj = 0; jj < 4; jj++) {
                int nr = jj * 16 + krow0;
                int chk = 2 * kk + kchkb;
                uint32_t addr = (uint32_t)(nr * 128) + (uint32_t)((chk ^ (nr & 7)) << 4);
                uint32_t bb[4];
                ldsm_x4(bb[0], bb[1], bb[2], bb[3], KHs + addr);
                mma16816(s[2 * jj],     qh[kk], bb + 0);
                mma16816(s[2 * jj + 1], qh[kk], bb + 2);
                mma16816(s[2 * jj],     ql[kk], bb + 0);
                mma16816(s[2 * jj + 1], ql[kk], bb + 2);
                ldsm_x4(bb[0], bb[1], bb[2], bb[3], KLs + addr);
                mma16816(s[2 * jj],     qh[kk], bb + 0);
                mma16816(s[2 * jj + 1], qh[kk], bb + 2);
            }
        }

#pragma unroll
        for (int t = 0; t < 8; t++)
#pragma unroll
            for (int i = 0; i < 4; i++) s[t][i] *= 0.125f;

        float rm0 = -INFINITY, rm1 = -INFINITY;
#pragma unroll
        for (int t = 0; t < 8; t++) {
            rm0 = fmaxf(rm0, fmaxf(s[t][0], s[t][1]));
            rm1 = fmaxf(rm1, fmaxf(s[t][2], s[t][3]));
        }
        rm0 = fmaxf(rm0, __shfl_xor_sync(0xffffffffu, rm0, 1));
        rm0 = fmaxf(rm0, __shfl_xor_sync(0xffffffffu, rm0, 2));
        rm1 = fmaxf(rm1, __shfl_xor_sync(0xffffffffu, rm1, 1));
        rm1 = fmaxf(rm1, __shfl_xor_sync(0xffffffffu, rm1, 2));

        float mn0 = fmaxf(m0, rm0), mn1 = fmaxf(m1, rm1);
        float cr0 = __expf(m0 - mn0), cr1 = __expf(m1 - mn1);
        float sum0 = 0.0f, sum1 = 0.0f;
#pragma unroll
        for (int t = 0; t < 8; t++) {
            s[t][0] = __expf(s[t][0] - mn0);
            s[t][1] = __expf(s[t][1] - mn0);
            s[t][2] = __expf(s[t][2] - mn1);
            s[t][3] = __expf(s[t][3] - mn1);
            sum0 += s[t][0] + s[t][1];
            sum1 += s[t][2] + s[t][3];
        }
        sum0 += __shfl_xor_sync(0xffffffffu, sum0, 1);
        sum0 += __shfl_xor_sync(0xffffffffu, sum0, 2);
        sum1 += __shfl_xor_sync(0xffffffffu, sum1, 1);
        sum1 += __shfl_xor_sync(0xffffffffu, sum1, 2);
        l0 = l0 * cr0 + sum0;
        l1 = l1 * cr1 + sum1;
#pragma unroll
        for (int t = 0; t < 8; t++) {
            o[t][0] *= cr0; o[t][1] *= cr0;
            o[t][2] *= cr1; o[t][3] *= cr1;
        }
        m0 = mn0; m1 = mn1;

#pragma unroll
        for (int kk = 0; kk < 4; kk++) {
            uint32_t ph[4], pl[4];
            {
                __nv_bfloat16 hi0, lo0, hi1, lo1;
                split_bf16(s[2 * kk][0], hi0, lo0);
                split_bf16(s[2 * kk][1], hi1, lo1);
                ph[0] = pack_bf2(hi0, hi1);  pl[0] = pack_bf2(lo0, lo1);
                split_bf16(s[2 * kk][2], hi0, lo0);
                split_bf16(s[2 * kk][3], hi1, lo1);
                ph[1] = pack_bf2(hi0, hi1);  pl[1] = pack_bf2(lo0, lo1);
                split_bf16(s[2 * kk + 1][0], hi0, lo0);
                split_bf16(s[2 * kk + 1][1], hi1, lo1);
                ph[2] = pack_bf2(hi0, hi1);  pl[2] = pack_bf2(lo0, lo1);
                split_bf16(s[2 * kk + 1][2], hi0, lo0);
                split_bf16(s[2 * kk + 1][3], hi1, lo1);
                ph[3] = pack_bf2(hi0, hi1);  pl[3] = pack_bf2(lo0, lo1);
            }
            int kr = kk * 16 + vrow0;
#pragma unroll
            for (int cp = 0; cp < 4; cp++) {
                int chk = 2 * cp + vchkb;
                uint32_t addr = (uint32_t)(kr * 128) + (uint32_t)((chk ^ (kr & 7)) << 4);
                uint32_t bv[4];
                ldsm_x4_t(bv[0], bv[1], bv[2], bv[3], VHs + addr);
                mma16816(o[2 * cp],     ph, bv + 0);
                mma16816(o[2 * cp + 1], ph, bv + 2);
                mma16816(o[2 * cp],     pl, bv + 0);
                mma16816(o[2 * cp + 1], pl, bv + 2);
                ldsm_x4_t(bv[0], bv[1], bv[2], bv[3], VLs + addr);
                mma16816(o[2 * cp],     ph, bv + 0);
                mma16816(o[2 * cp + 1], ph, bv + 2);
            }
        }
        __syncthreads();
    }

    float i0 = 1.0f / l0, i1 = 1.0f / l1;
    size_t g0 = (size_t)(b * SLEN + q0 + wid * 16 + (lane >> 2));
    size_t g1 = g0 + 8;
    int col0 = h * KHD + 2 * (lane & 3);
#pragma unroll
    for (int t = 0; t < 8; t++) {
        int col = col0 + t * 8;
        float v0 = o[t][0] * i0, v1 = o[t][1] * i0;
        float v2 = o[t][2] * i1, v3 = o[t][3] * i1;
        __nv_bfloat16 h0, ll0, h1, ll1;
        split_bf16(v0, h0, ll0); split_bf16(v1, h1, ll1);
        *(__nv_bfloat162*)(Oy + g0 * (2 * DDIM) + col)        = __halves2bfloat162(h0, h1);
        *(__nv_bfloat162*)(Oy + g0 * (2 * DDIM) + DDIM + col) = __halves2bfloat162(ll0, ll1);
        split_bf16(v2, h0, ll0); split_bf16(v3, h1, ll1);
        *(__nv_bfloat162*)(Oy + g1 * (2 * DDIM) + col)        = __halves2bfloat162(h0, h1);
        *(__nv_bfloat162*)(Oy + g1 * (2 * DDIM) + DDIM + col) = __halves2bfloat162(ll0, ll1);
    }
}

// ===================== MMA flash attention (compact experts, fp32 out) ======
__global__ __launch_bounds__(256)
void k_attn_mma_c(const __nv_bfloat16* __restrict__ qkvcbf,
                  float* __restrict__ cattf,
                  const int* __restrict__ cnt32, const int* __restrict__ seg32)
{
    const int e  = blockIdx.z;
    const int bh = blockIdx.y;
    const int b  = bh >> 3, h = bh & 7;
    const int cnt = __ldg(cnt32 + e * BNUM + b);
    const int q0  = blockIdx.x * 128;
    if (q0 >= cnt) return;
    const int seg = __ldg(seg32 + e * BNUM + b);

    const __nv_bfloat16* QKVs = qkvcbf + (size_t)e * MROWS * (2 * QKVW);
    float* Of = cattf + (size_t)e * CROWS * DDIM;

    extern __shared__ __align__(128) unsigned char smem[];
    const uint32_t sb = smem_u32(smem);
    const int tid = threadIdx.x, wid = tid >> 5, lane = tid & 31;

    const uint32_t QH = sb, QL = sb + 16384;

#pragma unroll
    for (int i = 0; i < 8; i++) {
        int id = tid + i * 256;
        int half = id >> 10, rem = id & 1023;
        int qr = rem >> 3, c = rem & 7;
        int qrow = q0 + qr; if (qrow >= cnt) qrow = cnt - 1;
        const __nv_bfloat16* src = QKVs
            + (size_t)(seg + qrow) * (2 * QKVW)
            + (size_t)half * QKVW + h * KHD + c * 8;
        cp16((half ? QL : QH) + qr * 128 + (uint32_t)((c ^ (qr & 7)) << 4), src);
    }
    asm volatile("cp.async.commit_group;" ::: "memory");

    const int NKC = (cnt + 63) >> 6;

    auto fillkv = [&](int kc) {
        uint32_t base = sb + 32768 + (uint32_t)(kc & 1) * 32768;
#pragma unroll
        for (int i = 0; i < 8; i++) {
            int id = tid + i * 256;
            int sub = id >> 9, rem = id & 511;
            int kr = rem >> 3, c = rem & 7;
            int col = (sub == 0) ? (DDIM + h * KHD)
                    : (sub == 1) ? (QKVW + DDIM + h * KHD)
                    : (sub == 2) ? (2 * DDIM + h * KHD)
                                 : (QKVW + 2 * DDIM + h * KHD);
            bool act = (kc * 64 + kr) < cnt;
            const void* src = act
                ? (const void*)(QKVs + (size_t)(seg + kc * 64 + kr) * (2 * QKVW) + col + c * 8)
                : (const void*)g_zerobuf;
            cp16(base + sub * 8192 + kr * 128 + (uint32_t)((c ^ (kr & 7)) << 4), src);
        }
        asm volatile("cp.async.commit_group;" ::: "memory");
    };

    fillkv(0);
    asm volatile("cp.async.wait_group 0;" ::: "memory");
    __syncthreads();

    uint32_t qh[4][4], ql[4][4];
    {
        int arow = wid * 16 + (lane & 15);
        int cb = lane >> 4;
#pragma unroll
        for (int kk = 0; kk < 4; kk++) {
            int chk = 2 * kk + cb;
            uint32_t off = (uint32_t)(arow * 128) + (uint32_t)((chk ^ (arow & 7)) << 4);
            ldsm_x4(qh[kk][0], qh[kk][1], qh[kk][2], qh[kk][3], QH + off);
            ldsm_x4(ql[kk][0], ql[kk][1], ql[kk][2], ql[kk][3], QL + off);
        }
    }

    float o[8][4];
#pragma unroll
    for (int t = 0; t < 8; t++)
#pragma unroll
        for (int i = 0; i < 4; i++) o[t][i] = 0.0f;
    float m0 = 0.0f, m1 = 0.0f;
    float l0 = (float)(SLEN - cnt), l1 = (float)(SLEN - cnt);

    const int krow0 = (lane & 7) + ((lane >> 4) << 3);
    const int kchkb = (lane >> 3) & 1;
    const int vrow0 = lane & 15;
    const int vchkb = lane >> 4;
    const int ncol0 = 2 * (lane & 3);

    for (int kc = 0; kc < NKC; kc++) {
        if (kc) {
            asm volatile("cp.async.wait_group 0;" ::: "memory");
            __syncthreads();
        }
        if (kc + 1 < NKC) fillkv(kc + 1);

        uint32_t KB  = sb + 32768 + (uint32_t)(kc & 1) * 32768;
        uint32_t KHs = KB, KLs = KB + 8192, VHs = KB + 16384, VLs = KB + 24576;

        float s[8][4];
#pragma unroll
        for (int t = 0; t < 8; t++)
#pragma unroll
            for (int i = 0; i < 4; i++) s[t][i] = 0.0f;

#pragma unroll
        for (int kk = 0; kk < 4; kk++) {
#pragma unroll
            for (int jj = 0; jj < 4; jj++) {
                int nr = jj * 16 + krow0;
                int chk = 2 * kk + kchkb;
                uint32_t addr = (uint32_t)(nr * 128) + (uint32_t)((chk ^ (nr & 7)) << 4);
                uint32_t bb[4];
                ldsm_x4(bb[0], bb[1], bb[2], bb[3], KHs + addr);
                mma16816(s[2 * jj],     qh[kk], bb + 0);
                mma16816(s[2 * jj + 1], qh[kk], bb + 2);
                mma16816(s[2 * jj],     ql[kk], bb + 0);
                mma16816(s[2 * jj + 1], ql[kk], bb + 2);
                ldsm_x4(bb[0], bb[1], bb[2], bb[3], KLs + addr);
                mma16816(s[2 * jj],     qh[kk], bb + 0);
                mma16816(s[2 * jj + 1], qh[kk], bb + 2);
            }
        }

        int rem = cnt - kc * 64;
#pragma unroll
        for (int t = 0; t < 8; t++) {
            int c0 = t * 8 + ncol0;
#pragma unroll
            for (int i = 0; i < 4; i++) {
                int colk = c0 + (i & 1);
                s[t][i] = (colk < rem) ? s[t][i] * 0.125f : -1e30f;
            }
        }

        float rm0 = -INFINITY, rm1 = -INFINITY;
#pragma unroll
        for (int t = 0; t < 8; t++) {
            rm0 = fmaxf(rm0, fmaxf(s[t][0], s[t][1]));
            rm1 = fmaxf(rm1, fmaxf(s[t][2], s[t][3]));
        }
        rm0 = fmaxf(rm0, __shfl_xor_sync(0xffffffffu, rm0, 1));
        rm0 = fmaxf(rm0, __shfl_xor_sync(0xffffffffu, rm0, 2));
        rm1 = fmaxf(rm1, __shfl_xor_sync(0xffffffffu, rm1, 1));
        rm1 = fmaxf(rm1, __shfl_xor_sync(0xffffffffu, rm1, 2));

        float mn0 = fmaxf(m0, rm0), mn1 = fmaxf(m1, rm1);
        float cr0 = __expf(m0 - mn0), cr1 = __expf(m1 - mn1);
        float sum0 = 0.0f, sum1 = 0.0f;
#pragma unroll
        for (int t = 0; t < 8; t++) {
            s[t][0] = __expf(s[t][0] - mn0);
            s[t][1] = __expf(s[t][1] - mn0);
            s[t][2] = __expf(s[t][2] - mn1);
            s[t][3] = __expf(s[t][3] - mn1);
            sum0 += s[t][0] + s[t][1];
            sum1 += s[t][2] + s[t][3];
        }
        sum0 += __shfl_xor_sync(0xffffffffu, sum0, 1);
        sum0 += __shfl_xor_sync(0xffffffffu, sum0, 2);
        sum1 += __shfl_xor_sync(0xffffffffu, sum1, 1);
        sum1 += __shfl_xor_sync(0xffffffffu, sum1, 2);
        l0 = l0 * cr0 + sum0;
        l1 = l1 * cr1 + sum1;
#pragma unroll
        for (int t = 0; t < 8; t++) {
            o[t][0] *= cr0; o[t][1] *= cr0;
            o[t][2] *= cr1; o[t][3] *= cr1;
        }
        m0 = mn0; m1 = mn1;

#pragma unroll
        for (int kk = 0; kk < 4; kk++) {
            uint32_t ph[4], pl[4];
            {
                __nv_bfloat16 hi0, lo0, hi1, lo1;
                split_bf16(s[2 * kk][0], hi0, lo0);
                split_bf16(s[2 * kk][1], hi1, lo1);
                ph[0] = pack_bf2(hi0, hi1);  pl[0] = pack_bf2(lo0, lo1);
                split_bf16(s[2 * kk][2], hi0, lo0);
                split_bf16(s[2 * kk][3], hi1, lo1);
                ph[1] = pack_bf2(hi0, hi1);  pl[1] = pack_bf2(lo0, lo1);
                split_bf16(s[2 * kk + 1][0], hi0, lo0);
                split_bf16(s[2 * kk + 1][1], hi1, lo1);
                ph[2] = pack_bf2(hi0, hi1);  pl[2] = pack_bf2(lo0, lo1);
                split_bf16(s[2 * kk + 1][2], hi0, lo0);
                split_bf16(s[2 * kk + 1][3], hi1, lo1);
                ph[3] = pack_bf2(hi0, hi1);  pl[3] = pack_bf2(lo0, lo1);
            }
            int kr = kk * 16 + vrow0;
#pragma unroll
            for (int cp = 0; cp < 4; cp++) {
                int chk = 2 * cp + vchkb;
                uint32_t addr = (uint32_t)(kr * 128) + (uint32_t)((chk ^ (kr & 7)) << 4);
                uint32_t bv[4];
                ldsm_x4_t(bv[0], bv[1], bv[2], bv[3], VHs + addr);
                mma16816(o[2 * cp],     ph, bv + 0);
                mma16816(o[2 * cp + 1], ph, bv + 2);
                mma16816(o[2 * cp],     pl, bv + 0);
                mma16816(o[2 * cp + 1], pl, bv + 2);
                ldsm_x4_t(bv[0], bv[1], bv[2], bv[3], VLs + addr);
                mma16816(o[2 * cp],     ph, bv + 0);
                mma16816(o[2 * cp + 1], ph, bv + 2);
            }
        }
        __syncthreads();
    }

    float i0 = 1.0f / l0, i1 = 1.0f / l1;
    int lr0 = q0 + wid * 16 + (lane >> 2);
    int lr1 = lr0 + 8;
    int col0 = h * KHD + 2 * (lane & 3);
#pragma unroll
    for (int t = 0; t < 8; t++) {
        int col = col0 + t * 8;
        if (lr0 < cnt)
            *(float2*)(Of + (size_t)(seg + lr0) * DDIM + col)
                = make_float2(o[t][0] * i0, o[t][1] * i0);
        if (lr1 < cnt)
            *(float2*)(Of + (size_t)(seg + lr1) * DDIM + col)
                = make_float2(o[t][2] * i1, o[t][3] * i1);
    }
}

// ===================== small fp32 GEMM: O[M,4] = A[M,K] @ B4[K,4] ===========
__global__ void k_mat4(const float* __restrict__ A, const float* __restrict__ B4,
                       float* __restrict__ O4, int K)
{
    int m = blockIdx.x * 8 + (threadIdx.x >> 5);
    int lane = threadIdx.x & 31;
    const float* ar = A + (size_t)m * K;
    float a0 = 0.f, a1 = 0.f, a2 = 0.f, a3 = 0.f;
    for (int k = lane; k < K; k += 32) {
        float a = ar[k];
        float4 b = *(const float4*)(B4 + (size_t)k * 4);
        a0 = fmaf(a, b.x, a0); a1 = fmaf(a, b.y, a1);
        a2 = fmaf(a, b.z, a2); a3 = fmaf(a, b.w, a3);
    }
#pragma unroll
    for (int off = 16; off; off >>= 1) {
        a0 += __shfl_down_sync(0xffffffffu, a0, off);
        a1 += __shfl_down_sync(0xffffffffu, a1, off);
        a2 += __shfl_down_sync(0xffffffffu, a2, off);
        a3 += __shfl_down_sync(0xffffffffu, a3, off);
    }
    if (lane == 0)
        *(float4*)(O4 + (size_t)m * 4) = make_float4(a0, a1, a2, a3);
}

// ===================== gate argmax (attbf @ c0, hi+lo reconstruct) ==========
__global__ void k_gate(const __nv_bfloat16* __restrict__ Hb, const float* __restrict__ Wg,
                       int* __restrict__ idx)
{
    int warp = (blockIdx.x * blockDim.x + threadIdx.x) >> 5;
    int lane = threadIdx.x & 31;
    if (warp >= MROWS) return;
    const __nv_bfloat16* hr = Hb + (size_t)warp * (2 * DDIM);
    float g[ENUM] = {0, 0, 0, 0};
    for (int d = lane; d < DDIM; d += 32) {
        float hv = __bfloat162float(hr[d]) + __bfloat162float(hr[DDIM + d]);
#pragma unroll
        for (int e = 0; e < ENUM; e++) g[e] = fmaf(hv, Wg[d * ENUM + e], g[e]);
    }
#pragma unroll
    for (int e = 0; e < ENUM; e++)
#pragma unroll
        for (int off = 16; off; off >>= 1)
            g[e] += __shfl_down_sync(0xffffffff, g[e], off);
    if (lane == 0) {
        int best = 0; float bv = g[0];
#pragma unroll
        for (int e = 1; e < ENUM; e++)
            if (g[e] > bv) { bv = g[e]; best = e; }
        idx[warp] = best;
    }
}

// ===================== compaction: scan / offsets ===========================
__global__ __launch_bounds__(1024)
void k_scan(const int* __restrict__ idx, int* __restrict__ pos, int* __restrict__ cnt)
{
    int e = blockIdx.x, b = blockIdx.y;
    int t = threadIdx.x;
    int token = b * SLEN + t;
    int p = (idx[token] == e) ? 1 : 0;
    int v = p;
#pragma unroll
    for (int o = 1; o < 32; o <<= 1) {
        int u = __shfl_up_sync(0xffffffffu, v, o);
        if ((t & 31) >= o) v += u;
    }
    __shared__ int wsum[32];
    if ((t & 31) == 31) wsum[t >> 5] = v;
    __syncthreads();
    if (t < 32) {
        int w = wsum[t];
#pragma unroll
        for (int o = 1; o < 32; o <<= 1) {
            int u = __shfl_up_sync(0xffffffffu, w, o);
            if (t >= o) w += u;
        }
        wsum[t] = w;
    }
    __syncthreads();
    int incl = v + ((t >= 32) ? wsum[(t >> 5) - 1] : 0);
    if (p) pos[token] = incl - 1;
    if (t == 1023) cnt[e * BNUM + b] = incl;
}

__global__ void k_off(const int* __restrict__ cnt, int* __restrict__ segoff,
                      int* __restrict__ ne)
{
    int e = threadIdx.x;
    if (e < ENUM) {
        int s = 0;
        for (int b = 0; b < BNUM; b++) { segoff[e * BNUM + b] = s; s += cnt[e * BNUM + b]; }
        ne[e] = s;
    }
}

// ===================== mean-v rows (from split qkv, fp32 out) ===============
__global__ __launch_bounds__(512)
void k_meanv(const __nv_bfloat16* __restrict__ qkvcbf, const int* __restrict__ cnt32,
             const int* __restrict__ seg32, const int* __restrict__ ne,
             float* __restrict__ cattf)
{
    __shared__ float4 part[4][128];
    int b = blockIdx.x, e = blockIdx.y;
    int cnt = __ldg(cnt32 + e * BNUM + b), seg = __ldg(seg32 + e * BNUM + b);
    const __nv_bfloat16* QKV = qkvcbf + (size_t)e * MROWS * (2 * QKVW);
    int c4 = threadIdx.x & 127, rg = threadIdx.x >> 7;
    int c = c4 * 4;
    float4 s = make_float4(0.f, 0.f, 0.f, 0.f);
    for (int r = rg; r < cnt; r += 4) {
        const __nv_bfloat16* row = QKV + (size_t)(seg + r) * (2 * QKVW);
        uint64_t uh = *(const uint64_t*)(row + 2 * DDIM + c);
        uint64_t ul = *(const uint64_t*)(row + QKVW + 2 * DDIM + c);
        const __nv_bfloat16* ph = (const __nv_bfloat16*)&uh;
        const __nv_bfloat16* pl = (const __nv_bfloat16*)&ul;
        s.x += __bfloat162float(ph[0]) + __bfloat162float(pl[0]);
        s.y += __bfloat162float(ph[1]) + __bfloat162float(pl[1]);
        s.z += __bfloat162float(ph[2]) + __bfloat162float(pl[2]);
        s.w += __bfloat162float(ph[3]) + __bfloat162float(pl[3]);
    }
    part[rg][c4] = s;
    __syncthreads();
    if (rg == 0) {
        float4 p1 = part[1][c4], p2 = part[2][c4], p3 = part[3][c4];
        s.x += p1.x + p2.x + p3.x;
        s.y += p1.y + p2.y + p3.y;
        s.z += p1.z + p2.z + p3.z;
        s.w += p1.w + p2.w + p3.w;
        const float is = 1.0f / (float)SLEN;
        int target = __ldg(ne + e) + b;
        float* row = cattf + ((size_t)e * CROWS + target) * DDIM + c;
        row[0] = s.x * is; row[1] = s.y * is;
        row[2] = s.z * is; row[3] = s.w * is;
    }
}

// ===================== mean scalars (catt mean rows . v0) ===================
__global__ __launch_bounds__(1024)
void k_msum2(const float* __restrict__ cattf, const int* __restrict__ ne,
             const float* __restrict__ v0,
             float* __restrict__ meanS, float* __restrict__ totalS)
{
    __shared__ float sh[ENUM * BNUM];
    int w = threadIdx.x >> 5, lane = threadIdx.x & 31;
    int e = w >> 3, b = w & 7;
    const float* row = cattf + ((size_t)e * CROWS + __ldg(ne + e) + b) * DDIM;
    const float* vv = v0 + e * DDIM;
    float s = 0.0f;
    for (int d = lane; d < DDIM; d += 32) s = fmaf(row[d], vv[d], s);
#pragma unroll
    for (int off = 16; off; off >>= 1) s += __shfl_down_sync(0xffffffff, s, off);
    if (lane == 0) { sh[w] = s; meanS[w] = s; }
    __syncthreads();
    if (threadIdx.x < BNUM) {
        float t = 0.0f;
        for (int e2 = 0; e2 < ENUM; e2++) t += sh[e2 * BNUM + threadIdx.x];
        totalS[threadIdx.x] = t;
    }
}

// ===================== final: catt . v0 + mean corrections ==================
__global__ void k_final3(const float* __restrict__ cattf, const int* __restrict__ idx,
                         const int* __restrict__ pos, const int* __restrict__ segoff,
                         const float* __restrict__ v0, const float* __restrict__ meanS,
                         const float* __restrict__ totalS, float* __restrict__ out)
{
    int warp = (blockIdx.x * blockDim.x + threadIdx.x) >> 5;
    int lane = threadIdx.x & 31;
    if (warp >= MROWS) return;
    int e = idx[warp], b = warp / SLEN;
    int slot = segoff[e * BNUM + b] + pos[warp];
    const float* r = cattf + ((size_t)e * CROWS + slot) * DDIM;
    const float* vv = v0 + e * DDIM;
    float s = 0.0f;
    for (int d = lane; d < DDIM; d += 32) s = fmaf(r[d], vv[d], s);
#pragma unroll
    for (int off = 16; off; off >>= 1) s += __shfl_down_sync(0xffffffff, s, off);
    if (lane == 0) out[warp] = s + totalS[b] - meanS[e * BNUM + b];
}

// ===================== host orchestration ===================================
extern "C" void kernel_launch(void* const* d_in, const int* in_sizes, int n_in,
                              void* d_out, int out_size)
{
    (void)in_sizes; (void)n_in; (void)out_size;
    const int*   tokens = (const int*)  d_in[0];
    const float* emb    = (const float*)d_in[1];
    const float* Wq     = (const float*)d_in[2];
    const float* Wk     = (const float*)d_in[3];
    const float* Wv     = (const float*)d_in[4];
    const float* Wo     = (const float*)d_in[5];
    const float* W1     = (const float*)d_in[6];
    const float* W2     = (const float*)d_in[7];
    const float* Wg     = (const float*)d_in[8];
    const float* eWq    = (const float*)d_in[9];
    const float* eWk    = (const float*)d_in[10];
    const float* eWv    = (const float*)d_in[11];
    const float* eWo    = (const float*)d_in[12];
    const float* eW1    = (const float*)d_in[13];
    const float* eW2    = (const float*)d_in[14];
    const float* Wout   = (const float*)d_in[15];
    float* out = (float*)d_out;

    __nv_bfloat16 *xbf, *qkvbf, *attbf, *cbfA, *qkvcbf;
    __nv_bfloat16 *swqkv, *sw1, *sw2, *swoA, *scmb1, *scmbB, *ewqkv;
    float *catt, *meanS, *totalS, *c2, *c1, *c0, *v2, *v1, *v0;
    int *idx, *cnt, *segoff, *ne, *pos;
    cudaGetSymbolAddress((void**)&xbf,    g_xbf);
    cudaGetSymbolAddress((void**)&qkvbf,  g_qkvbf);
    cudaGetSymbolAddress((void**)&attbf,  g_attbf);
    cudaGetSymbolAddress((void**)&idx,    g_idx);
    cudaGetSymbolAddress((void**)&cnt,    g_cnt);
    cudaGetSymbolAddress((void**)&segoff, g_segoff);
    cudaGetSymbolAddress((void**)&ne,     g_ne);
    cudaGetSymbolAddress((void**)&pos,    g_pos);
    cudaGetSymbolAddress((void**)&meanS,  g_meanS);
    cudaGetSymbolAddress((void**)&totalS, g_totalS);
    cudaGetSymbolAddress((void**)&c2,     g_c2);
    cudaGetSymbolAddress((void**)&c1,     g_c1);
    cudaGetSymbolAddress((void**)&c0,     g_c0);
    cudaGetSymbolAddress((void**)&v2,     g_v2);
    cudaGetSymbolAddress((void**)&v1,     g_v1);
    cudaGetSymbolAddress((void**)&v0,     g_v0);
    cudaGetSymbolAddress((void**)&cbfA,   g_cbfA);
    cudaGetSymbolAddress((void**)&qkvcbf, g_qkvcbf);
    cudaGetSymbolAddress((void**)&catt,   g_catt);
    cudaGetSymbolAddress((void**)&swqkv,  g_swqkv);
    cudaGetSymbolAddress((void**)&sw1,    g_sw1);
    cudaGetSymbolAddress((void**)&sw2,    g_sw2);
    cudaGetSymbolAddress((void**)&swoA,   g_swoA);
    cudaGetSymbolAddress((void**)&scmb1,  g_scmb1);
    cudaGetSymbolAddress((void**)&scmbB,  g_scmbB);
    cudaGetSymbolAddress((void**)&ewqkv,  g_ewqkv);

    cudaFuncSetAttribute(k_gemm3, cudaFuncAttributeMaxDynamicSharedMemorySize, G3_SMEM);
    cudaFuncSetAttribute(k_attn_mma, cudaFuncAttributeMaxDynamicSharedMemorySize, ATT_SMEM);
    cudaFuncSetAttribute(k_attn_mma_c, cudaFuncAttributeMaxDynamicSharedMemorySize, ATT_SMEM);

    static cudaStream_t s_side = nullptr;
    static cudaEvent_t  s_evFork = nullptr, s_evSw = nullptr, s_evC0 = nullptr,
                        s_evScmb = nullptr, s_evExp = nullptr,
                        s_evQc = nullptr, s_evMean = nullptr;
    if (!s_side) {
        cudaStreamCreateWithFlags(&s_side, cudaStreamNonBlocking);
        cudaEventCreateWithFlags(&s_evFork, cudaEventDisableTiming);
        cudaEventCreateWithFlags(&s_evSw,   cudaEventDisableTiming);
        cudaEventCreateWithFlags(&s_evC0,   cudaEventDisableTiming);
        cudaEventCreateWithFlags(&s_evScmb, cudaEventDisableTiming);
        cudaEventCreateWithFlags(&s_evExp,  cudaEventDisableTiming);
        cudaEventCreateWithFlags(&s_evQc,   cudaEventDisableTiming);
        cudaEventCreateWithFlags(&s_evMean, cudaEventDisableTiming);
    }

    dim3 tb32(32, 8);
    const size_t WQKV_SZ = (size_t)QKVW * 2 * DDIM;

    // ======== fork: side stream = all weight prep ========
    cudaEventRecord(s_evFork, 0);
    cudaStreamWaitEvent(s_side, s_evFork, 0);

    // side: shared qkv weight conversion FIRST (main's qkv GEMM waits on it)
    k_cvt_qkv<<<dim3(DDIM / 32, DDIM / 32, 3), tb32, 0, s_side>>>(Wq, Wk, Wv, 0, swqkv, 0);
    cudaEventRecord(s_evSw, s_side);

    // side: exact fp32 gate combo c0
    k_mat4<<<FFD / 8, 256, 0, s_side>>>(W2, Wg, c2, DDIM);
    k_mat4<<<DDIM / 8, 256, 0, s_side>>>(W1, c2, c1, FFD);
    k_mat4<<<DDIM / 8, 256, 0, s_side>>>(Wo, c1, c0, DDIM);
    cudaEventRecord(s_evC0, s_side);

    // side: shared FFN weights + shared combo
    k_cvt_wt<<<dim3(FFD / 32, DDIM / 32, 1), tb32, 0, s_side>>>(W1, 0, sw1, 0, DDIM, FFD);
    k_cvt_wt<<<dim3(DDIM / 32, FFD / 32, 1), tb32, 0, s_side>>>(W2, 0, sw2, 0, FFD, DDIM);
    k_cvt_a<<<dim3(256, 1, 1), 256, 0, s_side>>>(Wo, 0, swoA, 0);
    k_gemm3<<<dim3(FFD / 128, 4, 1), 256, G3_SMEM, s_side>>>(
        swoA, 0, sw1, 0, nullptr, 0, scmb1, 0, FFD, DDIM, nullptr, DDIM, 0,
        nullptr, nullptr, nullptr);
    k_gemm3<<<dim3(DDIM / 128, 4, 1), 256, G3_SMEM, s_side>>>(
        sw2, 0, scmb1, 0, nullptr, 0, scmbB, 0, DDIM, FFD, nullptr, DDIM, 0,
        nullptr, nullptr, nullptr);
    cudaEventRecord(s_evScmb, s_side);

    // side: expert qkv weights
    k_cvt_qkv<<<dim3(DDIM / 32, DDIM / 32, 3 * ENUM), tb32, 0, s_side>>>(
        eWq, eWk, eWv, (size_t)DDIM * DDIM, ewqkv, WQKV_SZ);
    cudaEventRecord(s_evExp, s_side);

    // side: exact fp32 expert out-vector v0 = eWo@(eW1@(eW2@Wout))
    k_matv<<<dim3(FFD / 8, 1, ENUM), 256, 0, s_side>>>(
        eW2, (size_t)FFD * DDIM, Wout, 0, v2, FFD, DDIM);
    k_matv<<<dim3(DDIM / 8, 1, ENUM), 256, 0, s_side>>>(
        eW1, (size_t)DDIM * FFD, v2, FFD, v1, DDIM, FFD);
    k_matv<<<dim3(DDIM / 8, 1, ENUM), 256, 0, s_side>>>(
        eWo, (size_t)DDIM * DDIM, v1, DDIM, v0, DDIM, DDIM);

    // ======== main stream: shared block + gate ========
    k_gather<<<(MROWS * (DDIM / 4)) / 256, 256>>>(tokens, emb, xbf);
    cudaStreamWaitEvent(0, s_evSw, 0);
    k_gemm3<<<dim3(QKVW / 128, MROWS / 128, 1), 256, G3_SMEM>>>(
        xbf, 0, swqkv, 0, nullptr, 0, qkvbf, 0, QKVW, DDIM, nullptr, MROWS, 0,
        nullptr, nullptr, nullptr);
    k_attn_mma<<<dim3(SLEN / 128, BNUM * HNUM), 256, ATT_SMEM>>>(qkvbf, attbf);

    cudaStreamWaitEvent(0, s_evC0, 0);
    k_gate<<<MROWS / 8, 256>>>(attbf, c0, idx);
    k_scan<<<dim3(ENUM, BNUM), 1024>>>(idx, pos, cnt);
    k_off<<<1, 32>>>(cnt, segoff, ne);

    // h-combo GEMM with scatter epilogue -> cbfA
    cudaStreamWaitEvent(0, s_evScmb, 0);
    k_gemm3<<<dim3(DDIM / 128, MROWS / 128, 1), 256, G3_SMEM>>>(
        attbf, 0, scmbB, 0, nullptr, 0, cbfA, 0, DDIM, DDIM, nullptr, MROWS, 0,
        idx, pos, segoff);

    // ======== experts ========
    cudaStreamWaitEvent(0, s_evExp, 0);
    k_gemm3<<<dim3(QKVW / 128, MROWS / 128, ENUM), 256, G3_SMEM>>>(
        cbfA, (size_t)MROWS * 2 * DDIM, ewqkv, WQKV_SZ,
        nullptr, 0, qkvcbf, (size_t)MROWS * 2 * QKVW, QKVW, DDIM, ne, 0, 0,
        nullptr, nullptr, nullptr);
    cudaEventRecord(s_evQc, 0);

    // side: mean rows + mean scalars overlap the expert attention below
    cudaStreamWaitEvent(s_side, s_evQc, 0);
    k_meanv<<<dim3(BNUM, ENUM), 512, 0, s_side>>>(qkvcbf, cnt, segoff, ne, catt);
    k_msum2<<<1, 1024, 0, s_side>>>(catt, ne, v0, meanS, totalS);
    cudaEventRecord(s_evMean, s_side);

    // main: compact expert attention (active rows of catt, disjoint from mean rows)
    k_attn_mma_c<<<dim3(SLEN / 128, BNUM * HNUM, ENUM), 256, ATT_SMEM>>>(
        qkvcbf, catt, cnt, segoff);

    // ---- final assembly ----
    cudaStreamWaitEvent(0, s_evMean, 0);
    k_final3<<<MROWS / 8, 256>>>(catt, idx, pos, segoff, v0, meanS, totalS, out);
}

// round 16
// speedup vs baseline: 1.0887x; 1.0263x over previous
#include <cuda_runtime.h>
#include <cuda_bf16.h>
#include <math.h>
#include <stdint.h>

// Problem constants
#define MROWS 8192      // B*S
#define DDIM  512
#define HNUM  8
#define KHD   64
#define FFD   2048
#define ENUM  4
#define SLEN  1024
#define BNUM  8
#define QKVW  1536
#define CROWS (MROWS + 128)   // compact rows + mean-row margin

// ===================== scratch (device globals) ==============================
__device__ __nv_bfloat16 g_xbf  [MROWS * 2 * DDIM];     // embedding, split
__device__ __nv_bfloat16 g_qkvbf[MROWS * 2 * QKVW];     // shared qkv, split
__device__ __nv_bfloat16 g_attbf[MROWS * 2 * DDIM];     // shared attn out split
__device__ __nv_bfloat16 g_hbf  [MROWS * 2 * DDIM];     // h = attbf@cmb, dense split
__device__ int   g_idx[MROWS];
__device__ int   g_cnt[ENUM * BNUM];
__device__ int   g_segoff[ENUM * BNUM];
__device__ int   g_ne[ENUM];
__device__ int   g_pos[MROWS];
__device__ int   g_s2t[ENUM * MROWS];                    // compact slot -> token
__device__ float g_meanS[ENUM * BNUM];
__device__ float g_totalS[BNUM];
__device__ float g_c2[FFD * ENUM];                       // W2@Wg
__device__ float g_c1[DDIM * ENUM];                      // W1@c2
__device__ float g_c0[DDIM * ENUM];                      // Wo@c1 (gate matrix)
__device__ float g_v2[ENUM * FFD];                       // eW2@Wout
__device__ float g_v1[ENUM * DDIM];                      // eW1@v2
__device__ float g_v0[ENUM * DDIM];                      // eWo@v1 (expert out vector)
__device__ __align__(16) unsigned char g_zerobuf[16];

// per-expert compact buffers
__device__ __nv_bfloat16 g_qkvcbf[ENUM * MROWS * 2 * QKVW];  // compact qkv split
__device__ float         g_catt  [ENUM * CROWS * DDIM];      // compact attn + mean rows

// weights: bf16 hi|lo split. *_T = transposed [N, 2K]; *_A = row-split [M, 2K]
__device__ __nv_bfloat16 g_swqkv[QKVW * 2 * DDIM];
__device__ __nv_bfloat16 g_sw1  [FFD  * 2 * DDIM];
__device__ __nv_bfloat16 g_sw2  [DDIM * 2 * FFD];
__device__ __nv_bfloat16 g_swoA [DDIM * 2 * DDIM];
__device__ __nv_bfloat16 g_scmb1[DDIM * 2 * FFD];        // Wo@W1 split
__device__ __nv_bfloat16 g_scmbB[DDIM * 2 * DDIM];       // (Wo@W1@W2)^T-format
__device__ __nv_bfloat16 g_ewqkv[ENUM * QKVW * 2 * DDIM];

// ===================== PTX helpers (base ISA only) ==========================
__device__ __forceinline__ uint32_t smem_u32(const void* p) {
    uint32_t a;
    asm("{ .reg .u64 t; cvta.to.shared.u64 t, %1; cvt.u32.u64 %0, t; }"
        : "=r"(a) : "l"(p));
    return a;
}
__device__ __forceinline__ void cp16(uint32_t dst, const void* src) {
    asm volatile("cp.async.cg.shared.global [%0], [%1], 16;"
                 :: "r"(dst), "l"(src) : "memory");
}
__device__ __forceinline__ void ldsm_x4(uint32_t& r0, uint32_t& r1,
                                        uint32_t& r2, uint32_t& r3, uint32_t addr) {
    asm volatile("ldmatrix.sync.aligned.m8n8.x4.shared.b16 {%0,%1,%2,%3}, [%4];"
                 : "=r"(r0), "=r"(r1), "=r"(r2), "=r"(r3) : "r"(addr));
}
__device__ __forceinline__ void ldsm_x4_t(uint32_t& r0, uint32_t& r1,
                                          uint32_t& r2, uint32_t& r3, uint32_t addr) {
    asm volatile("ldmatrix.sync.aligned.m8n8.x4.trans.shared.b16 {%0,%1,%2,%3}, [%4];"
                 : "=r"(r0), "=r"(r1), "=r"(r2), "=r"(r3) : "r"(addr));
}
__device__ __forceinline__ void mma16816(float* c, const uint32_t* a, const uint32_t* b) {
    asm volatile("mma.sync.aligned.m16n8k16.row.col.f32.bf16.bf16.f32 "
                 "{%0,%1,%2,%3}, {%4,%5,%6,%7}, {%8,%9}, {%0,%1,%2,%3};"
                 : "+f"(c[0]), "+f"(c[1]), "+f"(c[2]), "+f"(c[3])
                 : "r"(a[0]), "r"(a[1]), "r"(a[2]), "r"(a[3]),
                   "r"(b[0]), "r"(b[1]));
}
__device__ __forceinline__ void split_bf16(float x, __nv_bfloat16& hi, __nv_bfloat16& lo) {
    hi = __float2bfloat16(x);
    lo = __float2bfloat16(x - __bfloat162float(hi));
}
__device__ __forceinline__ uint32_t pack_bf2(__nv_bfloat16 a, __nv_bfloat16 b) {
    __nv_bfloat162 t = __halves2bfloat162(a, b);
    return *(uint32_t*)&t;
}

// ===================== embedding gather (split output) ======================
__global__ void k_gather(const int* __restrict__ tok,
                         const float* __restrict__ emb,
                         __nv_bfloat16* __restrict__ xbf)
{
    int t  = blockIdx.x * blockDim.x + threadIdx.x;
    int i  = t >> 7;
    int c4 = t & 127;
    float4 v = ((const float4*)(emb + (size_t)tok[i] * DDIM))[c4];
    float xv[4] = {v.x, v.y, v.z, v.w};
    __nv_bfloat16 hi[4], lo[4];
#pragma unroll
    for (int j = 0; j < 4; j++) split_bf16(xv[j], hi[j], lo[j]);
    __nv_bfloat16* row = xbf + (size_t)i * (2 * DDIM);
    *(uint64_t*)(row + c4 * 4)        = *(uint64_t*)hi;
    *(uint64_t*)(row + DDIM + c4 * 4) = *(uint64_t*)lo;
}

// ===================== weight conversion kernels ============================
__global__ void k_cvt_wt(const float* __restrict__ W, size_t wSz,
                         __nv_bfloat16* __restrict__ Y, size_t ySz,
                         int K, int N)
{
    W += (size_t)blockIdx.z * wSz;
    Y += (size_t)blockIdx.z * ySz;
    __shared__ float tile[32][33];
    int k0 = blockIdx.y * 32, n0 = blockIdx.x * 32;
    int tx = threadIdx.x, ty = threadIdx.y;   // 32 x 8
#pragma unroll
    for (int i = 0; i < 32; i += 8)
        tile[ty + i][tx] = W[(size_t)(k0 + ty + i) * N + n0 + tx];
    __syncthreads();
#pragma unroll
    for (int i = 0; i < 32; i += 8) {
        float x = tile[tx][ty + i];
        __nv_bfloat16 hi, lo; split_bf16(x, hi, lo);
        size_t base = (size_t)(n0 + ty + i) * (2 * K) + k0 + tx;
        Y[base]     = hi;
        Y[base + K] = lo;
    }
}

__global__ void k_cvt_qkv(const float* __restrict__ Wq_, const float* __restrict__ Wk_,
                          const float* __restrict__ Wv_, size_t wSz,
                          __nv_bfloat16* __restrict__ Y, size_t ySz)
{
    int e = blockIdx.z / 3, which = blockIdx.z % 3;
    const float* W = (which == 0) ? Wq_ : (which == 1) ? Wk_ : Wv_;
    W += (size_t)e * wSz;
    __nv_bfloat16* Yp = Y + (size_t)e * ySz + (size_t)which * (DDIM * 2 * DDIM);
    __shared__ float tile[32][33];
    int k0 = blockIdx.y * 32, n0 = blockIdx.x * 32;
    int tx = threadIdx.x, ty = threadIdx.y;
#pragma unroll
    for (int i = 0; i < 32; i += 8)
        tile[ty + i][tx] = W[(size_t)(k0 + ty + i) * DDIM + n0 + tx];
    __syncthreads();
#pragma unroll
    for (int i = 0; i < 32; i += 8) {
        float x = tile[tx][ty + i];
        __nv_bfloat16 hi, lo; split_bf16(x, hi, lo);
        size_t base = (size_t)(n0 + ty + i) * (2 * DDIM) + k0 + tx;
        Yp[base]        = hi;
        Yp[base + DDIM] = lo;
    }
}

__global__ void k_cvt_a(const float* __restrict__ W, size_t wSz,
                        __nv_bfloat16* __restrict__ Y, size_t ySz)
{
    W += (size_t)blockIdx.z * wSz;
    Y += (size_t)blockIdx.z * ySz;
    int t  = blockIdx.x * blockDim.x + threadIdx.x;
    int r  = t >> 7;
    int c4 = t & 127;
    float4 v = ((const float4*)(W + (size_t)r * DDIM))[c4];
    float xv[4] = {v.x, v.y, v.z, v.w};
    __nv_bfloat16 hi[4], lo[4];
#pragma unroll
    for (int j = 0; j < 4; j++) split_bf16(xv[j], hi[j], lo[j]);
    __nv_bfloat16* row = Y + (size_t)r * (2 * DDIM);
    *(uint64_t*)(row + c4 * 4)        = *(uint64_t*)hi;
    *(uint64_t*)(row + DDIM + c4 * 4) = *(uint64_t*)lo;
}

// ===================== fp32 matvec: o[r] = W[r,:] . v (z-batched) ===========
__global__ void k_matv(const float* __restrict__ W, size_t wSz,
                       const float* __restrict__ v, size_t vSz,
                       float* __restrict__ o, size_t oSz, int K)
{
    W += (size_t)blockIdx.z * wSz;
    v += (size_t)blockIdx.z * vSz;
    o += (size_t)blockIdx.z * oSz;
    int r = blockIdx.x * 8 + (threadIdx.x >> 5);
    int lane = threadIdx.x & 31;
    const float* wr = W + (size_t)r * K;
    float s = 0.0f;
    for (int k = lane; k < K; k += 32) s = fmaf(wr[k], v[k], s);
#pragma unroll
    for (int off = 16; off; off >>= 1) s += __shfl_down_sync(0xffffffffu, s, off);
    if (lane == 0) o[r] = s;
}

// ===================== mma.sync bf16x3 GEMM — fused 3-product ===============
// Optional A-row gather: when s2t != null, A row r of expert z comes from
// Ag[ __ldg(s2t + z*MROWS + r) ] (Ag dense per-token, aSz must be 0).
#define G3_STAGE 32768
#define G3_SMEM  (3 * G3_STAGE)

__global__ __launch_bounds__(256, 2)
void k_gemm3(const __nv_bfloat16* __restrict__ Ag, size_t aSz,
             const __nv_bfloat16* __restrict__ Bg, size_t bSz,
             float* __restrict__ Cf, size_t cSz,
             __nv_bfloat16* __restrict__ Y, size_t ySz,
             int N, int K,
             const int* __restrict__ nptr, int nconst, int nadd,
             const int* __restrict__ s2t)
{
    const int z = blockIdx.z;
    Ag += (size_t)z * aSz;
    Bg += (size_t)z * bSz;
    const int n = (nptr ? __ldg(nptr + z) : nconst) + nadd;
    const int mbase = blockIdx.y * 128;
    if (mbase >= n) return;
    if (Cf) Cf += (size_t)z * cSz;
    if (Y)  Y  += (size_t)z * ySz;
    const int* s2tz = s2t ? (s2t + (size_t)z * MROWS) : nullptr;

    extern __shared__ __align__(128) unsigned char smem[];
    const uint32_t sbase = smem_u32(smem);
    const int tid  = threadIdx.x;
    const int wid  = tid >> 5;
    const int lane = tid & 31;

    const int nbase = blockIdx.x * 128;
    const int K2    = 2 * K;
    const int NCP   = K / 32;

    const int mo = (wid >> 2) * 64;
    const int no = (wid & 3) * 32;

    auto fill = [&](int c) {
        int s   = c % 3;
        int col = c * 32;
        uint32_t base = sbase + s * G3_STAGE;
#pragma unroll
        for (int i2 = 0; i2 < 2; i2++) {
            int ch = tid + i2 * 256;
            int r  = ch >> 2, cc = ch & 3;
            uint32_t off = (uint32_t)(r * 64) + (uint32_t)((cc ^ ((r >> 1) & 3)) << 4);
            int grow = mbase + r;
            bool act = grow < n;
            int arowi = (s2tz && act) ? __ldg(s2tz + grow) : grow;
            const __nv_bfloat16* arow = Ag + (size_t)arowi * K2 + col + cc * 8;
            cp16(base + off, act ? (const void*)arow : (const void*)g_zerobuf);
            cp16(base + 8192 + off, act ? (const void*)(arow + K) : (const void*)g_zerobuf);
            const __nv_bfloat16* brow = Bg + (size_t)(nbase + r) * K2 + col + cc * 8;
            cp16(base + 16384 + off, brow);
            cp16(base + 24576 + off, brow + K);
        }
        asm volatile("cp.async.commit_group;" ::: "memory");
    };

    float acc[4][4][4];
#pragma unroll
    for (int i = 0; i < 4; i++)
#pragma unroll
        for (int j = 0; j < 4; j++)
#pragma unroll
            for (int t = 0; t < 4; t++) acc[i][j][t] = 0.0f;

    fill(0);
    if (NCP > 1) fill(1);

    for (int c = 0; c < NCP; c++) {
        if (c + 1 < NCP) asm volatile("cp.async.wait_group 1;" ::: "memory");
        else             asm volatile("cp.async.wait_group 0;" ::: "memory");
        __syncthreads();

        if (c + 2 < NCP) fill(c + 2);

        uint32_t sA = sbase + (c % 3) * G3_STAGE;
        uint32_t sB = sA + 16384;

#pragma unroll
        for (int kk = 0; kk < 2; kk++) {
            uint32_t a[4][4];
            uint32_t b[4][2];
            int achk = 2 * kk + (lane >> 4);
            int arow0 = lane & 15;
            int bchk = 2 * kk + ((lane >> 3) & 1);
            int brow0 = (lane & 7) + ((lane >> 4) << 3);

#pragma unroll
            for (int i = 0; i < 4; i++) {
                int row = mo + i * 16 + arow0;
                ldsm_x4(a[i][0], a[i][1], a[i][2], a[i][3],
                        sA + row * 64 + (uint32_t)(((achk ^ ((row >> 1) & 3))) << 4));
            }
#pragma unroll
            for (int jj = 0; jj < 2; jj++) {
                int nrow = no + jj * 16 + brow0;
                ldsm_x4(b[2 * jj][0], b[2 * jj][1], b[2 * jj + 1][0], b[2 * jj + 1][1],
                        sB + nrow * 64 + (uint32_t)(((bchk ^ ((nrow >> 1) & 3))) << 4));
            }
#pragma unroll
            for (int i = 0; i < 4; i++)
#pragma unroll
                for (int j = 0; j < 4; j++)
                    mma16816(acc[i][j], a[i], b[j]);

#pragma unroll
            for (int i = 0; i < 4; i++) {
                int row = mo + i * 16 + arow0;
                ldsm_x4(a[i][0], a[i][1], a[i][2], a[i][3],
                        sA + 8192 + row * 64 + (uint32_t)(((achk ^ ((row >> 1) & 3))) << 4));
            }
#pragma unroll
            for (int i = 0; i < 4; i++)
#pragma unroll
                for (int j = 0; j < 4; j++)
                    mma16816(acc[i][j], a[i], b[j]);

#pragma unroll
            for (int i = 0; i < 4; i++) {
                int row = mo + i * 16 + arow0;
                ldsm_x4(a[i][0], a[i][1], a[i][2], a[i][3],
                        sA + row * 64 + (uint32_t)(((achk ^ ((row >> 1) & 3))) << 4));
            }
#pragma unroll
            for (int jj = 0; jj < 2; jj++) {
                int nrow = no + jj * 16 + brow0;
                ldsm_x4(b[2 * jj][0], b[2 * jj][1], b[2 * jj + 1][0], b[2 * jj + 1][1],
                        sA + 24576 + nrow * 64 + (uint32_t)(((bchk ^ ((nrow >> 1) & 3))) << 4));
            }
#pragma unroll
            for (int i = 0; i < 4; i++)
#pragma unroll
                for (int j = 0; j < 4; j++)
                    mma16816(acc[i][j], a[i], b[j]);
        }
    }

    int rbase = mbase + mo + (lane >> 2);
    int cbase = nbase + no + (lane & 3) * 2;
#pragma unroll
    for (int i = 0; i < 4; i++) {
        int r0 = rbase + i * 16, r1 = r0 + 8;
#pragma unroll
        for (int j = 0; j < 4; j++) {
            int col = cbase + j * 8;
            if (Cf) {
                if (r0 < n)
                    *(float2*)(Cf + (size_t)r0 * N + col) = make_float2(acc[i][j][0], acc[i][j][1]);
                if (r1 < n)
                    *(float2*)(Cf + (size_t)r1 * N + col) = make_float2(acc[i][j][2], acc[i][j][3]);
            }
            if (Y) {
                if (r0 < n) {
                    __nv_bfloat16 h0, l0, h1, l1;
                    split_bf16(acc[i][j][0], h0, l0);
                    split_bf16(acc[i][j][1], h1, l1);
                    *(__nv_bfloat162*)(Y + (size_t)r0 * 2 * N + col)     = __halves2bfloat162(h0, h1);
                    *(__nv_bfloat162*)(Y + (size_t)r0 * 2 * N + N + col) = __halves2bfloat162(l0, l1);
                }
                if (r1 < n) {
                    __nv_bfloat16 h0, l0, h1, l1;
                    split_bf16(acc[i][j][2], h0, l0);
                    split_bf16(acc[i][j][3], h1, l1);
                    *(__nv_bfloat162*)(Y + (size_t)r1 * 2 * N + col)     = __halves2bfloat162(h0, h1);
                    *(__nv_bfloat162*)(Y + (size_t)r1 * 2 * N + N + col) = __halves2bfloat162(l0, l1);
                }
            }
        }
    }
}

// ===================== MMA flash attention (shared block) ===================
#define ATT_SMEM 98304   // Q 32KB + 2 x (K/V hi/lo 32KB)

__global__ __launch_bounds__(256)
void k_attn_mma(const __nv_bfloat16* __restrict__ QKVs,
                __nv_bfloat16* __restrict__ Oy)
{
    extern __shared__ __align__(128) unsigned char smem[];
    const uint32_t sb = smem_u32(smem);
    const int tid = threadIdx.x, wid = tid >> 5, lane = tid & 31;
    const int bh = blockIdx.y, b = bh >> 3, h = bh & 7;
    const int q0 = blockIdx.x * 128;

    const uint32_t QH = sb, QL = sb + 16384;

#pragma unroll
    for (int i = 0; i < 8; i++) {
        int id = tid + i * 256;
        int half = id >> 10, rem = id & 1023;
        int qr = rem >> 3, c = rem & 7;
        const __nv_bfloat16* src = QKVs
            + (size_t)(b * SLEN + q0 + qr) * (2 * QKVW)
            + (size_t)half * QKVW + h * KHD + c * 8;
        cp16((half ? QL : QH) + qr * 128 + (uint32_t)((c ^ (qr & 7)) << 4), src);
    }
    asm volatile("cp.async.commit_group;" ::: "memory");

    auto fillkv = [&](int kc) {
        uint32_t base = sb + 32768 + (uint32_t)(kc & 1) * 32768;
#pragma unroll
        for (int i = 0; i < 8; i++) {
            int id = tid + i * 256;
            int sub = id >> 9, rem = id & 511;
            int kr = rem >> 3, c = rem & 7;
            int col = (sub == 0) ? (DDIM + h * KHD)
                    : (sub == 1) ? (QKVW + DDIM + h * KHD)
                    : (sub == 2) ? (2 * DDIM + h * KHD)
                                 : (QKVW + 2 * DDIM + h * KHD);
            const __nv_bfloat16* src = QKVs
                + (size_t)(b * SLEN + kc * 64 + kr) * (2 * QKVW) + col + c * 8;
            cp16(base + sub * 8192 + kr * 128 + (uint32_t)((c ^ (kr & 7)) << 4), src);
        }
        asm volatile("cp.async.commit_group;" ::: "memory");
    };

    fillkv(0);
    asm volatile("cp.async.wait_group 0;" ::: "memory");
    __syncthreads();

    uint32_t qh[4][4], ql[4][4];
    {
        int arow = wid * 16 + (lane & 15);
        int cb = lane >> 4;
#pragma unroll
        for (int kk = 0; kk < 4; kk++) {
            int chk = 2 * kk + cb;
            uint32_t off = (uint32_t)(arow * 128) + (uint32_t)((chk ^ (arow & 7)) << 4);
            ldsm_x4(qh[kk][0], qh[kk][1], qh[kk][2], qh[kk][3], QH + off);
            ldsm_x4(ql[kk][0], ql[kk][1], ql[kk][2], ql[kk][3], QL + off);
        }
    }

    float o[8][4];
#pragma unroll
    for (int t = 0; t < 8; t++)
#pragma unroll
        for (int i = 0; i < 4; i++) o[t][i] = 0.0f;
    float m0 = -INFINITY, m1 = -INFINITY, l0 = 0.0f, l1 = 0.0f;

    const int krow0 = (lane & 7) + ((lane >> 4) << 3);
    const int kchkb = (lane >> 3) & 1;
    const int vrow0 = lane & 15;
    const int vchkb = lane >> 4;

    for (int kc = 0; kc < 16; kc++) {
        if (kc) {
            asm volatile("cp.async.wait_group 0;" ::: "memory");
            __syncthreads();
        }
        if (kc + 1 < 16) fillkv(kc + 1);

        uint32_t KB  = sb + 32768 + (uint32_t)(kc & 1) * 32768;
        uint32_t KHs = KB, KLs = KB + 8192, VHs = KB + 16384, VLs = KB + 24576;

        float s[8][4];
#pragma unroll
        for (int t = 0; t < 8; t++)
#pragma unroll
            for (int i = 0; i < 4; i++) s[t][i] = 0.0f;

#pragma unroll
        for (int kk = 0; kk < 4; kk++) {
#pragma unroll
            for (int jj = 0; jj < 4; jj++) {
                int nr = jj * 16 + krow0;
                int chk = 2 * kk + kchkb;
                uint32_t addr = (uint32_t)(nr * 128) + (uint32_t)((chk ^ (nr & 7)) << 4);
                uint32_t bb[4];
                ldsm_x4(bb[0], bb[1], bb[2], bb[3], KHs + addr);
                mma16816(s[2 * jj],     qh[kk], bb + 0);
                mma16816(s[2 * jj + 1], qh[kk], bb + 2);
                mma16816(s[2 * jj],     ql[kk], bb + 0);
                mma16816(s[2 * jj + 1], ql[kk], bb + 2);
                ldsm_x4(bb[0], bb[1], bb[2], bb[3], KLs + addr);
                mma16816(s[2 * jj],     qh[kk], bb + 0);
                mma16816(s[2 * jj + 1], qh[kk], bb + 2);
            }
        }

#pragma unroll
        for (int t = 0; t < 8; t++)
#pragma unroll
            for (int i = 0; i < 4; i++) s[t][i] *= 0.125f;

        float rm0 = -INFINITY, rm1 = -INFINITY;
#pragma unroll
        for (int t = 0; t < 8; t++) {
            rm0 = fmaxf(rm0, fmaxf(s[t][0], s[t][1]));
            rm1 = fmaxf(rm1, fmaxf(s[t][2], s[t][3]));
        }
        rm0 = fmaxf(rm0, __shfl_xor_sync(0xffffffffu, rm0, 1));
        rm0 = fmaxf(rm0, __shfl_xor_sync(0xffffffffu, rm0, 2));
        rm1 = fmaxf(rm1, __shfl_xor_sync(0xffffffffu, rm1, 1));
        rm1 = fmaxf(rm1, __shfl_xor_sync(0xffffffffu, rm1, 2));

        float mn0 = fmaxf(m0, rm0), mn1 = fmaxf(m1, rm1);
        float cr0 = __expf(m0 - mn0), cr1 = __expf(m1 - mn1);
        float sum0 = 0.0f, sum1 = 0.0f;
#pragma unroll
        for (int t = 0; t < 8; t++) {
            s[t][0] = __expf(s[t][0] - mn0);
            s[t][1] = __expf(s[t][1] - mn0);
            s[t][2] = __expf(s[t][2] - mn1);
            s[t][3] = __expf(s[t][3] - mn1);
            sum0 += s[t][0] + s[t][1];
            sum1 += s[t][2] + s[t][3];
        }
        sum0 += __shfl_xor_sync(0xffffffffu, sum0, 1);
        sum0 += __shfl_xor_sync(0xffffffffu, sum0, 2);
        sum1 += __shfl_xor_sync(0xffffffffu, sum1, 1);
        sum1 += __shfl_xor_sync(0xffffffffu, sum1, 2);
        l0 = l0 * cr0 + sum0;
        l1 = l1 * cr1 + sum1;
#pragma unroll
        for (int t = 0; t < 8; t++) {
            o[t][0] *= cr0; o[t][1] *= cr0;
            o[t][2] *= cr1; o[t][3] *= cr1;
        }
        m0 = mn0; m1 = mn1;

#pragma unroll
        for (int kk = 0; kk < 4; kk++) {
            uint32_t ph[4], pl[4];
            {
                __nv_bfloat16 hi0, lo0, hi1, lo1;
                split_bf16(s[2 * kk][0], hi0, lo0);
                split_bf16(s[2 * kk][1], hi1, lo1);
                ph[0] = pack_bf2(hi0, hi1);  pl[0] = pack_bf2(lo0, lo1);
                split_bf16(s[2 * kk][2], hi0, lo0);
                split_bf16(s[2 * kk][3], hi1, lo1);
                ph[1] = pack_bf2(hi0, hi1);  pl[1] = pack_bf2(lo0, lo1);
                split_bf16(s[2 * kk + 1][0], hi0, lo0);
                split_bf16(s[2 * kk + 1][1], hi1, lo1);
                ph[2] = pack_bf2(hi0, hi1);  pl[2] = pack_bf2(lo0, lo1);
                split_bf16(s[2 * kk + 1][2], hi0, lo0);
                split_bf16(s[2 * kk + 1][3], hi1, lo1);
                ph[3] = pack_bf2(hi0, hi1);  pl[3] = pack_bf2(lo0, lo1);
            }
            int kr = kk * 16 + vrow0;
#pragma unroll
            for (int cp = 0; cp < 4; cp++) {
                int chk = 2 * cp + vchkb;
                uint32_t addr = (uint32_t)(kr * 128) + (uint32_t)((chk ^ (kr & 7)) << 4);
                uint32_t bv[4];
                ldsm_x4_t(bv[0], bv[1], bv[2], bv[3], VHs + addr);
                mma16816(o[2 * cp],     ph, bv + 0);
                mma16816(o[2 * cp + 1], ph, bv + 2);
                mma16816(o[2 * cp],     pl, bv + 0);
                mma16816(o[2 * cp + 1], pl, bv + 2);
                ldsm_x4_t(bv[0], bv[1], bv[2], bv[3], VLs + addr);
                mma16816(o[2 * cp],     ph, bv + 0);
                mma16816(o[2 * cp + 1], ph, bv + 2);
            }
        }
        __syncthreads();
    }

    float i0 = 1.0f / l0, i1 = 1.0f / l1;
    size_t g0 = (size_t)(b * SLEN + q0 + wid * 16 + (lane >> 2));
    size_t g1 = g0 + 8;
    int col0 = h * KHD + 2 * (lane & 3);
#pragma unroll
    for (int t = 0; t < 8; t++) {
        int col = col0 + t * 8;
        float v0 = o[t][0] * i0, v1 = o[t][1] * i0;
        float v2 = o[t][2] * i1, v3 = o[t][3] * i1;
        __nv_bfloat16 h0, ll0, h1, ll1;
        split_bf16(v0, h0, ll0); split_bf16(v1, h1, ll1);
        *(__nv_bfloat162*)(Oy + g0 * (2 * DDIM) + col)        = __halves2bfloat162(h0, h1);
        *(__nv_bfloat162*)(Oy + g0 * (2 * DDIM) + DDIM + col) = __halves2bfloat162(ll0, ll1);
        split_bf16(v2, h0, ll0); split_bf16(v3, h1, ll1);
        *(__nv_bfloat162*)(Oy + g1 * (2 * DDIM) + col)        = __halves2bfloat162(h0, h1);
        *(__nv_bfloat162*)(Oy + g1 * (2 * DDIM) + DDIM + col) = __halves2bfloat162(ll0, ll1);
    }
}

// ===================== MMA flash attention (compact experts, fp32 out) ======
__global__ __launch_bounds__(256)
void k_attn_mma_c(const __nv_bfloat16* __restrict__ qkvcbf,
                  float* __restrict__ cattf,
                  const int* __restrict__ cnt32, const int* __restrict__ seg32)
{
    const int e  = blockIdx.z;
    const int bh = blockIdx.y;
    const int b  = bh >> 3, h = bh & 7;
    const int cnt = __ldg(cnt32 + e * BNUM + b);
    const int q0  = blockIdx.x * 128;
    if (q0 >= cnt) return;
    const int seg = __ldg(seg32 + e * BNUM + b);

    const __nv_bfloat16* QKVs = qkvcbf + (size_t)e * MROWS * (2 * QKVW);
    float* Of = cattf + (size_t)e * CROWS * DDIM;

    extern __shared__ __align__(128) unsigned char smem[];
    const uint32_t sb = smem_u32(smem);
    const int tid = threadIdx.x, wid = tid >> 5, lane = tid & 31;

    const uint32_t QH = sb, QL = sb + 16384;

#pragma unroll
    for (int i = 0; i < 8; i++) {
        int id = tid + i * 256;
        int half = id >> 10, rem = id & 1023;
        int qr = rem >> 3, c = rem & 7;
        int qrow = q0 + qr; if (qrow >= cnt) qrow = cnt - 1;
        const __nv_bfloat16* src = QKVs
            + (size_t)(seg + qrow) * (2 * QKVW)
            + (size_t)half * QKVW + h * KHD + c * 8;
        cp16((half ? QL : QH) + qr * 128 + (uint32_t)((c ^ (qr & 7)) << 4), src);
    }
    asm volatile("cp.async.commit_group;" ::: "memory");

    const int NKC = (cnt + 63) >> 6;

    auto fillkv = [&](int kc) {
        uint32_t base = sb + 32768 + (uint32_t)(kc & 1) * 32768;
#pragma unroll
        for (int i = 0; i < 8; i++) {
            int id = tid + i * 256;
            int sub = id >> 9, rem = id & 511;
            int kr = rem >> 3, c = rem & 7;
            int col = (sub == 0) ? (DDIM + h * KHD)
                    : (sub == 1) ? (QKVW + DDIM + h * KHD)
                    : (sub == 2) ? (2 * DDIM + h * KHD)
                                 : (QKVW + 2 * DDIM + h * KHD);
            bool act = (kc * 64 + kr) < cnt;
            const void* src = act
                ? (const void*)(QKVs + (size_t)(seg + kc * 64 + kr) * (2 * QKVW) + col + c * 8)
                : (const void*)g_zerobuf;
            cp16(base + sub * 8192 + kr * 128 + (uint32_t)((c ^ (kr & 7)) << 4), src);
        }
        asm volatile("cp.async.commit_group;" ::: "memory");
    };

    fillkv(0);
    asm volatile("cp.async.wait_group 0;" ::: "memory");
    __syncthreads();

    uint32_t qh[4][4], ql[4][4];
    {
        int arow = wid * 16 + (lane & 15);
        int cb = lane >> 4;
#pragma unroll
        for (int kk = 0; kk < 4; kk++) {
            int chk = 2 * kk + cb;
            uint32_t off = (uint32_t)(arow * 128) + (uint32_t)((chk ^ (arow & 7)) << 4);
            ldsm_x4(qh[kk][0], qh[kk][1], qh[kk][2], qh[kk][3], QH + off);
            ldsm_x4(ql[kk][0], ql[kk][1], ql[kk][2], ql[kk][3], QL + off);
        }
    }

    float o[8][4];
#pragma unroll
    for (int t = 0; t < 8; t++)
#pragma unroll
        for (int i = 0; i < 4; i++) o[t][i] = 0.0f;
    float m0 = 0.0f, m1 = 0.0f;
    float l0 = (float)(SLEN - cnt), l1 = (float)(SLEN - cnt);

    const int krow0 = (lane & 7) + ((lane >> 4) << 3);
    const int kchkb = (lane >> 3) & 1;
    const int vrow0 = lane & 15;
    const int vchkb = lane >> 4;
    const int ncol0 = 2 * (lane & 3);

    for (int kc = 0; kc < NKC; kc++) {
        if (kc) {
            asm volatile("cp.async.wait_group 0;" ::: "memory");
            __syncthreads();
        }
        if (kc + 1 < NKC) fillkv(kc + 1);

        uint32_t KB  = sb + 32768 + (uint32_t)(kc & 1) * 32768;
        uint32_t KHs = KB, KLs = KB + 8192, VHs = KB + 16384, VLs = KB + 24576;

        float s[8][4];
#pragma unroll
        for (int t = 0; t < 8; t++)
#pragma unroll
            for (int i = 0; i < 4; i++) s[t][i] = 0.0f;

#pragma unroll
        for (int kk = 0; kk < 4; kk++) {
#pragma unroll
            for (int jj = 0; jj < 4; jj++) {
                int nr = jj * 16 + krow0;
                int chk = 2 * kk + kchkb;
                uint32_t addr = (uint32_t)(nr * 128) + (uint32_t)((chk ^ (nr & 7)) << 4);
                uint32_t bb[4];
                ldsm_x4(bb[0], bb[1], bb[2], bb[3], KHs + addr);
                mma16816(s[2 * jj],     qh[kk], bb + 0);
                mma16816(s[2 * jj + 1], qh[kk], bb + 2);
                mma16816(s[2 * jj],     ql[kk], bb + 0);
                mma16816(s[2 * jj + 1], ql[kk], bb + 2);
                ldsm_x4(bb[0], bb[1], bb[2], bb[3], KLs + addr);
                mma16816(s[2 * jj],     qh[kk], bb + 0);
                mma16816(s[2 * jj + 1], qh[kk], bb + 2);
            }
        }

        int rem = cnt - kc * 64;
#pragma unroll
        for (int t = 0; t < 8; t++) {
            int c0 = t * 8 + ncol0;
#pragma unroll
            for (int i = 0; i < 4; i++) {
                int colk = c0 + (i & 1);
                s[t][i] = (colk < rem) ? s[t][i] * 0.125f : -1e30f;
            }
        }

        float rm0 = -INFINITY, rm1 = -INFINITY;
#pragma unroll
        for (int t = 0; t < 8; t++) {
            rm0 = fmaxf(rm0, fmaxf(s[t][0], s[t][1]));
            rm1 = fmaxf(rm1, fmaxf(s[t][2], s[t][3]));
        }
        rm0 = fmaxf(rm0, __shfl_xor_sync(0xffffffffu, rm0, 1));
        rm0 = fmaxf(rm0, __shfl_xor_sync(0xffffffffu, rm0, 2));
        rm1 = fmaxf(rm1, __shfl_xor_sync(0xffffffffu, rm1, 1));
        rm1 = fmaxf(rm1, __shfl_xor_sync(0xffffffffu, rm1, 2));

        float mn0 = fmaxf(m0, rm0), mn1 = fmaxf(m1, rm1);
        float cr0 = __expf(m0 - mn0), cr1 = __expf(m1 - mn1);
        float sum0 = 0.0f, sum1 = 0.0f;
#pragma unroll
        for (int t = 0; t < 8; t++) {
            s[t][0] = __expf(s[t][0] - mn0);
            s[t][1] = __expf(s[t][1] - mn0);
            s[t][2] = __expf(s[t][2] - mn1);
            s[t][3] = __expf(s[t][3] - mn1);
            sum0 += s[t][0] + s[t][1];
            sum1 += s[t][2] + s[t][3];
        }
        sum0 += __shfl_xor_sync(0xffffffffu, sum0, 1);
        sum0 += __shfl_xor_sync(0xffffffffu, sum0, 2);
        sum1 += __shfl_xor_sync(0xffffffffu, sum1, 1);
        sum1 += __shfl_xor_sync(0xffffffffu, sum1, 2);
        l0 = l0 * cr0 + sum0;
        l1 = l1 * cr1 + sum1;
#pragma unroll
        for (int t = 0; t < 8; t++) {
            o[t][0] *= cr0; o[t][1] *= cr0;
            o[t][2] *= cr1; o[t][3] *= cr1;
        }
        m0 = mn0; m1 = mn1;

#pragma unroll
        for (int kk = 0; kk < 4; kk++) {
            uint32_t ph[4], pl[4];
            {
                __nv_bfloat16 hi0, lo0, hi1, lo1;
                split_bf16(s[2 * kk][0], hi0, lo0);
                split_bf16(s[2 * kk][1], hi1, lo1);
                ph[0] = pack_bf2(hi0, hi1);  pl[0] = pack_bf2(lo0, lo1);
                split_bf16(s[2 * kk][2], hi0, lo0);
                split_bf16(s[2 * kk][3], hi1, lo1);
                ph[1] = pack_bf2(hi0, hi1);  pl[1] = pack_bf2(lo0, lo1);
                split_bf16(s[2 * kk + 1][0], hi0, lo0);
                split_bf16(s[2 * kk + 1][1], hi1, lo1);
                ph[2] = pack_bf2(hi0, hi1);  pl[2] = pack_bf2(lo0, lo1);
                split_bf16(s[2 * kk + 1][2], hi0, lo0);
                split_bf16(s[2 * kk + 1][3], hi1, lo1);
                ph[3] = pack_bf2(hi0, hi1);  pl[3] = pack_bf2(lo0, lo1);
            }
            int kr = kk * 16 + vrow0;
#pragma unroll
            for (int cp = 0; cp < 4; cp++) {
                int chk = 2 * cp + vchkb;
                uint32_t addr = (uint32_t)(kr * 128) + (uint32_t)((chk ^ (kr & 7)) << 4);
                uint32_t bv[4];
                ldsm_x4_t(bv[0], bv[1], bv[2], bv[3], VHs + addr);
                mma16816(o[2 * cp],     ph, bv + 0);
                mma16816(o[2 * cp + 1], ph, bv + 2);
                mma16816(o[2 * cp],     pl, bv + 0);
                mma16816(o[2 * cp + 1], pl, bv + 2);
                ldsm_x4_t(bv[0], bv[1], bv[2], bv[3], VLs + addr);
                mma16816(o[2 * cp],     ph, bv + 0);
                mma16816(o[2 * cp + 1], ph, bv + 2);
            }
        }
        __syncthreads();
    }

    float i0 = 1.0f / l0, i1 = 1.0f / l1;
    int lr0 = q0 + wid * 16 + (lane >> 2);
    int lr1 = lr0 + 8;
    int col0 = h * KHD + 2 * (lane & 3);
#pragma unroll
    for (int t = 0; t < 8; t++) {
        int col = col0 + t * 8;
        if (lr0 < cnt)
            *(float2*)(Of + (size_t)(seg + lr0) * DDIM + col)
                = make_float2(o[t][0] * i0, o[t][1] * i0);
        if (lr1 < cnt)
            *(float2*)(Of + (size_t)(seg + lr1) * DDIM + col)
                = make_float2(o[t][2] * i1, o[t][3] * i1);
    }
}

// ===================== small fp32 GEMM: O[M,4] = A[M,K] @ B4[K,4] ===========
__global__ void k_mat4(const float* __restrict__ A, const float* __restrict__ B4,
                       float* __restrict__ O4, int K)
{
    int m = blockIdx.x * 8 + (threadIdx.x >> 5);
    int lane = threadIdx.x & 31;
    const float* ar = A + (size_t)m * K;
    float a0 = 0.f, a1 = 0.f, a2 = 0.f, a3 = 0.f;
    for (int k = lane; k < K; k += 32) {
        float a = ar[k];
        float4 b = *(const float4*)(B4 + (size_t)k * 4);
        a0 = fmaf(a, b.x, a0); a1 = fmaf(a, b.y, a1);
        a2 = fmaf(a, b.z, a2); a3 = fmaf(a, b.w, a3);
    }
#pragma unroll
    for (int off = 16; off; off >>= 1) {
        a0 += __shfl_down_sync(0xffffffffu, a0, off);
        a1 += __shfl_down_sync(0xffffffffu, a1, off);
        a2 += __shfl_down_sync(0xffffffffu, a2, off);
        a3 += __shfl_down_sync(0xffffffffu, a3, off);
    }
    if (lane == 0)
        *(float4*)(O4 + (size_t)m * 4) = make_float4(a0, a1, a2, a3);
}

// ===================== gate argmax (attbf @ c0, hi+lo reconstruct) ==========
__global__ void k_gate(const __nv_bfloat16* __restrict__ Hb, const float* __restrict__ Wg,
                       int* __restrict__ idx)
{
    int warp = (blockIdx.x * blockDim.x + threadIdx.x) >> 5;
    int lane = threadIdx.x & 31;
    if (warp >= MROWS) return;
    const __nv_bfloat16* hr = Hb + (size_t)warp * (2 * DDIM);
    float g[ENUM] = {0, 0, 0, 0};
    for (int d = lane; d < DDIM; d += 32) {
        float hv = __bfloat162float(hr[d]) + __bfloat162float(hr[DDIM + d]);
#pragma unroll
        for (int e = 0; e < ENUM; e++) g[e] = fmaf(hv, Wg[d * ENUM + e], g[e]);
    }
#pragma unroll
    for (int e = 0; e < ENUM; e++)
#pragma unroll
        for (int off = 16; off; off >>= 1)
            g[e] += __shfl_down_sync(0xffffffff, g[e], off);
    if (lane == 0) {
        int best = 0; float bv = g[0];
#pragma unroll
        for (int e = 1; e < ENUM; e++)
            if (g[e] > bv) { bv = g[e]; best = e; }
        idx[warp] = best;
    }
}

// ===================== compaction: scan / offsets / slot2tok ================
__global__ __launch_bounds__(1024)
void k_scan(const int* __restrict__ idx, int* __restrict__ pos, int* __restrict__ cnt)
{
    int e = blockIdx.x, b = blockIdx.y;
    int t = threadIdx.x;
    int token = b * SLEN + t;
    int p = (idx[token] == e) ? 1 : 0;
    int v = p;
#pragma unroll
    for (int o = 1; o < 32; o <<= 1) {
        int u = __shfl_up_sync(0xffffffffu, v, o);
        if ((t & 31) >= o) v += u;
    }
    __shared__ int wsum[32];
    if ((t & 31) == 31) wsum[t >> 5] = v;
    __syncthreads();
    if (t < 32) {
        int w = wsum[t];
#pragma unroll
        for (int o = 1; o < 32; o <<= 1) {
            int u = __shfl_up_sync(0xffffffffu, w, o);
            if (t >= o) w += u;
        }
        wsum[t] = w;
    }
    __syncthreads();
    int incl = v + ((t >= 32) ? wsum[(t >> 5) - 1] : 0);
    if (p) pos[token] = incl - 1;
    if (t == 1023) cnt[e * BNUM + b] = incl;
}

__global__ void k_off(const int* __restrict__ cnt, int* __restrict__ segoff,
                      int* __restrict__ ne)
{
    int e = threadIdx.x;
    if (e < ENUM) {
        int s = 0;
        for (int b = 0; b < BNUM; b++) { segoff[e * BNUM + b] = s; s += cnt[e * BNUM + b]; }
        ne[e] = s;
    }
}

__global__ void k_s2t(const int* __restrict__ idx, const int* __restrict__ pos,
                      const int* __restrict__ segoff, int* __restrict__ s2t)
{
    int t = blockIdx.x * blockDim.x + threadIdx.x;
    int e = idx[t], b = t / SLEN;
    s2t[(size_t)e * MROWS + segoff[e * BNUM + b] + pos[t]] = t;
}

// ===================== mean-v rows (from split qkv, fp32 out) ===============
__global__ __launch_bounds__(512)
void k_meanv(const __nv_bfloat16* __restrict__ qkvcbf, const int* __restrict__ cnt32,
             const int* __restrict__ seg32, const int* __restrict__ ne,
             float* __restrict__ cattf)
{
    __shared__ float4 part[4][128];
    int b = blockIdx.x, e = blockIdx.y;
    int cnt = __ldg(cnt32 + e * BNUM + b), seg = __ldg(seg32 + e * BNUM + b);
    const __nv_bfloat16* QKV = qkvcbf + (size_t)e * MROWS * (2 * QKVW);
    int c4 = threadIdx.x & 127, rg = threadIdx.x >> 7;
    int c = c4 * 4;
    float4 s = make_float4(0.f, 0.f, 0.f, 0.f);
    for (int r = rg; r < cnt; r += 4) {
        const __nv_bfloat16* row = QKV + (size_t)(seg + r) * (2 * QKVW);
        uint64_t uh = *(const uint64_t*)(row + 2 * DDIM + c);
        uint64_t ul = *(const uint64_t*)(row + QKVW + 2 * DDIM + c);
        const __nv_bfloat16* ph = (const __nv_bfloat16*)&uh;
        const __nv_bfloat16* pl = (const __nv_bfloat16*)&ul;
        s.x += __bfloat162float(ph[0]) + __bfloat162float(pl[0]);
        s.y += __bfloat162float(ph[1]) + __bfloat162float(pl[1]);
        s.z += __bfloat162float(ph[2]) + __bfloat162float(pl[2]);
        s.w += __bfloat162float(ph[3]) + __bfloat162float(pl[3]);
    }
    part[rg][c4] = s;
    __syncthreads();
    if (rg == 0) {
        float4 p1 = part[1][c4], p2 = part[2][c4], p3 = part[3][c4];
        s.x += p1.x + p2.x + p3.x;
        s.y += p1.y + p2.y + p3.y;
        s.z += p1.z + p2.z + p3.z;
        s.w += p1.w + p2.w + p3.w;
        const float is = 1.0f / (float)SLEN;
        int target = __ldg(ne + e) + b;
        float* row = cattf + ((size_t)e * CROWS + target) * DDIM + c;
        row[0] = s.x * is; row[1] = s.y * is;
        row[2] = s.z * is; row[3] = s.w * is;
    }
}

// ===================== mean scalars (catt mean rows . v0) ===================
__global__ __launch_bounds__(1024)
void k_msum2(const float* __restrict__ cattf, const int* __restrict__ ne,
             const float* __restrict__ v0,
             float* __restrict__ meanS, float* __restrict__ totalS)
{
    __shared__ float sh[ENUM * BNUM];
    int w = threadIdx.x >> 5, lane = threadIdx.x & 31;
    int e = w >> 3, b = w & 7;
    const float* row = cattf + ((size_t)e * CROWS + __ldg(ne + e) + b) * DDIM;
    const float* vv = v0 + e * DDIM;
    float s = 0.0f;
    for (int d = lane; d < DDIM; d += 32) s = fmaf(row[d], vv[d], s);
#pragma unroll
    for (int off = 16; off; off >>= 1) s += __shfl_down_sync(0xffffffff, s, off);
    if (lane == 0) { sh[w] = s; meanS[w] = s; }
    __syncthreads();
    if (threadIdx.x < BNUM) {
        float t = 0.0f;
        for (int e2 = 0; e2 < ENUM; e2++) t += sh[e2 * BNUM + threadIdx.x];
        totalS[threadIdx.x] = t;
    }
}

// ===================== final: catt . v0 + mean corrections ==================
__global__ void k_final3(const float* __restrict__ cattf, const int* __restrict__ idx,
                         const int* __restrict__ pos, const int* __restrict__ segoff,
                         const float* __restrict__ v0, const float* __restrict__ meanS,
                         const float* __restrict__ totalS, float* __restrict__ out)
{
    int warp = (blockIdx.x * blockDim.x + threadIdx.x) >> 5;
    int lane = threadIdx.x & 31;
    if (warp >= MROWS) return;
    int e = idx[warp], b = warp / SLEN;
    int slot = segoff[e * BNUM + b] + pos[warp];
    const float* r = cattf + ((size_t)e * CROWS + slot) * DDIM;
    const float* vv = v0 + e * DDIM;
    float s = 0.0f;
    for (int d = lane; d < DDIM; d += 32) s = fmaf(r[d], vv[d], s);
#pragma unroll
    for (int off = 16; off; off >>= 1) s += __shfl_down_sync(0xffffffff, s, off);
    if (lane == 0) out[warp] = s + totalS[b] - meanS[e * BNUM + b];
}

// ===================== host orchestration ===================================
extern "C" void kernel_launch(void* const* d_in, const int* in_sizes, int n_in,
                              void* d_out, int out_size)
{
    (void)in_sizes; (void)n_in; (void)out_size;
    const int*   tokens = (const int*)  d_in[0];
    const float* emb    = (const float*)d_in[1];
    const float* Wq     = (const float*)d_in[2];
    const float* Wk     = (const float*)d_in[3];
    const float* Wv     = (const float*)d_in[4];
    const float* Wo     = (const float*)d_in[5];
    const float* W1     = (const float*)d_in[6];
    const float* W2     = (const float*)d_in[7];
    const float* Wg     = (const float*)d_in[8];
    const float* eWq    = (const float*)d_in[9];
    const float* eWk    = (const float*)d_in[10];
    const float* eWv    = (const float*)d_in[11];
    const float* eWo    = (const float*)d_in[12];
    const float* eW1    = (const float*)d_in[13];
    const float* eW2    = (const float*)d_in[14];
    const float* Wout   = (const float*)d_in[15];
    float* out = (float*)d_out;

    __nv_bfloat16 *xbf, *qkvbf, *attbf, *hbf, *qkvcbf;
    __nv_bfloat16 *swqkv, *sw1, *sw2, *swoA, *scmb1, *scmbB, *ewqkv;
    float *catt, *meanS, *totalS, *c2, *c1, *c0, *v2, *v1, *v0;
    int *idx, *cnt, *segoff, *ne, *pos, *s2t;
    cudaGetSymbolAddress((void**)&xbf,    g_xbf);
    cudaGetSymbolAddress((void**)&qkvbf,  g_qkvbf);
    cudaGetSymbolAddress((void**)&attbf,  g_attbf);
    cudaGetSymbolAddress((void**)&hbf,    g_hbf);
    cudaGetSymbolAddress((void**)&idx,    g_idx);
    cudaGetSymbolAddress((void**)&cnt,    g_cnt);
    cudaGetSymbolAddress((void**)&segoff, g_segoff);
    cudaGetSymbolAddress((void**)&ne,     g_ne);
    cudaGetSymbolAddress((void**)&pos,    g_pos);
    cudaGetSymbolAddress((void**)&s2t,    g_s2t);
    cudaGetSymbolAddress((void**)&meanS,  g_meanS);
    cudaGetSymbolAddress((void**)&totalS, g_totalS);
    cudaGetSymbolAddress((void**)&c2,     g_c2);
    cudaGetSymbolAddress((void**)&c1,     g_c1);
    cudaGetSymbolAddress((void**)&c0,     g_c0);
    cudaGetSymbolAddress((void**)&v2,     g_v2);
    cudaGetSymbolAddress((void**)&v1,     g_v1);
    cudaGetSymbolAddress((void**)&v0,     g_v0);
    cudaGetSymbolAddress((void**)&qkvcbf, g_qkvcbf);
    cudaGetSymbolAddress((void**)&catt,   g_catt);
    cudaGetSymbolAddress((void**)&swqkv,  g_swqkv);
    cudaGetSymbolAddress((void**)&sw1,    g_sw1);
    cudaGetSymbolAddress((void**)&sw2,    g_sw2);
    cudaGetSymbolAddress((void**)&swoA,   g_swoA);
    cudaGetSymbolAddress((void**)&scmb1,  g_scmb1);
    cudaGetSymbolAddress((void**)&scmbB,  g_scmbB);
    cudaGetSymbolAddress((void**)&ewqkv,  g_ewqkv);

    cudaFuncSetAttribute(k_gemm3, cudaFuncAttributeMaxDynamicSharedMemorySize, G3_SMEM);
    cudaFuncSetAttribute(k_attn_mma, cudaFuncAttributeMaxDynamicSharedMemorySize, ATT_SMEM);
    cudaFuncSetAttribute(k_attn_mma_c, cudaFuncAttributeMaxDynamicSharedMemorySize, ATT_SMEM);

    static cudaStream_t s_side = nullptr;
    static cudaEvent_t  s_evFork = nullptr, s_evSw = nullptr, s_evC0 = nullptr,
                        s_evScmb = nullptr, s_evExp = nullptr,
                        s_evAtt = nullptr, s_evGate = nullptr,
                        s_evQc = nullptr, s_evMean = nullptr;
    if (!s_side) {
        cudaStreamCreateWithFlags(&s_side, cudaStreamNonBlocking);
        cudaEventCreateWithFlags(&s_evFork, cudaEventDisableTiming);
        cudaEventCreateWithFlags(&s_evSw,   cudaEventDisableTiming);
        cudaEventCreateWithFlags(&s_evC0,   cudaEventDisableTiming);
        cudaEventCreateWithFlags(&s_evScmb, cudaEventDisableTiming);
        cudaEventCreateWithFlags(&s_evExp,  cudaEventDisableTiming);
        cudaEventCreateWithFlags(&s_evAtt,  cudaEventDisableTiming);
        cudaEventCreateWithFlags(&s_evGate, cudaEventDisableTiming);
        cudaEventCreateWithFlags(&s_evQc,   cudaEventDisableTiming);
        cudaEventCreateWithFlags(&s_evMean, cudaEventDisableTiming);
    }

    dim3 tb32(32, 8);
    const size_t WQKV_SZ = (size_t)QKVW * 2 * DDIM;

    // ======== fork: side stream = all weight prep ========
    cudaEventRecord(s_evFork, 0);
    cudaStreamWaitEvent(s_side, s_evFork, 0);

    // side: shared qkv weight conversion FIRST (main's qkv GEMM waits on it)
    k_cvt_qkv<<<dim3(DDIM / 32, DDIM / 32, 3), tb32, 0, s_side>>>(Wq, Wk, Wv, 0, swqkv, 0);
    cudaEventRecord(s_evSw, s_side);

    // side: exact fp32 gate combo c0
    k_mat4<<<FFD / 8, 256, 0, s_side>>>(W2, Wg, c2, DDIM);
    k_mat4<<<DDIM / 8, 256, 0, s_side>>>(W1, c2, c1, FFD);
    k_mat4<<<DDIM / 8, 256, 0, s_side>>>(Wo, c1, c0, DDIM);
    cudaEventRecord(s_evC0, s_side);

    // side: shared FFN weights + shared combo
    k_cvt_wt<<<dim3(FFD / 32, DDIM / 32, 1), tb32, 0, s_side>>>(W1, 0, sw1, 0, DDIM, FFD);
    k_cvt_wt<<<dim3(DDIM / 32, FFD / 32, 1), tb32, 0, s_side>>>(W2, 0, sw2, 0, FFD, DDIM);
    k_cvt_a<<<dim3(256, 1, 1), 256, 0, s_side>>>(Wo, 0, swoA, 0);
    k_gemm3<<<dim3(FFD / 128, 4, 1), 256, G3_SMEM, s_side>>>(
        swoA, 0, sw1, 0, nullptr, 0, scmb1, 0, FFD, DDIM, nullptr, DDIM, 0, nullptr);
    k_gemm3<<<dim3(DDIM / 128, 4, 1), 256, G3_SMEM, s_side>>>(
        sw2, 0, scmb1, 0, nullptr, 0, scmbB, 0, DDIM, FFD, nullptr, DDIM, 0, nullptr);
    cudaEventRecord(s_evScmb, s_side);

    // side: expert qkv weights
    k_cvt_qkv<<<dim3(DDIM / 32, DDIM / 32, 3 * ENUM), tb32, 0, s_side>>>(
        eWq, eWk, eWv, (size_t)DDIM * DDIM, ewqkv, WQKV_SZ);
    cudaEventRecord(s_evExp, s_side);

    // side: exact fp32 expert out-vector v0 = eWo@(eW1@(eW2@Wout))
    k_matv<<<dim3(FFD / 8, 1, ENUM), 256, 0, s_side>>>(
        eW2, (size_t)FFD * DDIM, Wout, 0, v2, FFD, DDIM);
    k_matv<<<dim3(DDIM / 8, 1, ENUM), 256, 0, s_side>>>(
        eW1, (size_t)DDIM * FFD, v2, FFD, v1, DDIM, FFD);
    k_matv<<<dim3(DDIM / 8, 1, ENUM), 256, 0, s_side>>>(
        eWo, (size_t)DDIM * DDIM, v1, DDIM, v0, DDIM, DDIM);

    // ======== main stream: shared block ========
    k_gather<<<(MROWS * (DDIM / 4)) / 256, 256>>>(tokens, emb, xbf);
    cudaStreamWaitEvent(0, s_evSw, 0);
    k_gemm3<<<dim3(QKVW / 128, MROWS / 128, 1), 256, G3_SMEM>>>(
        xbf, 0, swqkv, 0, nullptr, 0, qkvbf, 0, QKVW, DDIM, nullptr, MROWS, 0, nullptr);
    k_attn_mma<<<dim3(SLEN / 128, BNUM * HNUM), 256, ATT_SMEM>>>(qkvbf, attbf);
    cudaEventRecord(s_evAtt, 0);

    // side: gate chain overlaps main's h-combo GEMM below
    cudaStreamWaitEvent(s_side, s_evAtt, 0);
    cudaStreamWaitEvent(s_side, s_evC0, 0);
    k_gate<<<MROWS / 8, 256, 0, s_side>>>(attbf, c0, idx);
    k_scan<<<dim3(ENUM, BNUM), 1024, 0, s_side>>>(idx, pos, cnt);
    k_off<<<1, 32, 0, s_side>>>(cnt, segoff, ne);
    k_s2t<<<MROWS / 256, 256, 0, s_side>>>(idx, pos, segoff, s2t);
    cudaEventRecord(s_evGate, s_side);

    // main: h-combo GEMM, dense split output (no scatter dependency)
    cudaStreamWaitEvent(0, s_evScmb, 0);
    k_gemm3<<<dim3(DDIM / 128, MROWS / 128, 1), 256, G3_SMEM>>>(
        attbf, 0, scmbB, 0, nullptr, 0, hbf, 0, DDIM, DDIM, nullptr, MROWS, 0, nullptr);

    // ======== experts: gathered-A qkv GEMM ========
    cudaStreamWaitEvent(0, s_evGate, 0);
    cudaStreamWaitEvent(0, s_evExp, 0);
    k_gemm3<<<dim3(QKVW / 128, MROWS / 128, ENUM), 256, G3_SMEM>>>(
        hbf, 0, ewqkv, WQKV_SZ,
        nullptr, 0, qkvcbf, (size_t)MROWS * 2 * QKVW, QKVW, DDIM, ne, 0, 0, s2t);
    cudaEventRecord(s_evQc, 0);

    // side: mean rows + mean scalars overlap the expert attention below
    cudaStreamWaitEvent(s_side, s_evQc, 0);
    k_meanv<<<dim3(BNUM, ENUM), 512, 0, s_side>>>(qkvcbf, cnt, segoff, ne, catt);
    k_msum2<<<1, 1024, 0, s_side>>>(catt, ne, v0, meanS, totalS);
    cudaEventRecord(s_evMean, s_side);

    // main: compact expert attention (active rows of catt, disjoint from mean rows)
    k_attn_mma_c<<<dim3(SLEN / 128, BNUM * HNUM, ENUM), 256, ATT_SMEM>>>(
        qkvcbf, catt, cnt, segoff);

    // ---- final assembly ----
    cudaStreamWaitEvent(0, s_evMean, 0);
    k_final3<<<MROWS / 8, 256>>>(catt, idx, pos, segoff, v0, meanS, totalS, out);
}